// round 1
// baseline (speedup 1.0000x reference)
#include <cuda_runtime.h>
#include <math.h>

// Problem constants
#define Bc 16
#define Nc 1024
#define Hc 4
#define KVc 960
#define Dc 240            // KV/4, per-head K/V feature dim

#define SZ_BHND (Bc*Hc*Nc*Dc)   // 15,728,640

// ---------------- scratch (static device globals; no allocation) ----------
__device__ float g_heads[SZ_BHND];          // [B,H,N,240]
__device__ float g_Kh   [SZ_BHND];          // [B,H,N,240]
__device__ float g_Vh   [SZ_BHND];          // [B,H,N,240]
__device__ float g_Qh   [SZ_BHND];          // per-scale blocks [B,H,N,d]
__device__ float g_S    [Bc*Hc*Dc*Dc];      // per-scale blocks [B,H,d,240]
__device__ float g_ctx  [SZ_BHND];          // per-scale blocks [B,H,d,N]
__device__ float g_ctxT [Bc*Nc*KVc];        // per-scale blocks [B,N,CH]

// ---------------- GEMM config ----------------
#define BM 64
#define BN 64
#define BK 16
#define NTHR 256

// C[m,n] = alpha * sum_k A[m,k] * B[n,k]   (A row-major [M,K], B row-major [Nn,K])
// batched via blockIdx.z; batch offset = (z/Hs)*xB + (z%Hs)*xH
__global__ __launch_bounds__(NTHR)
void gemm_nt(const float* __restrict__ A, const float* __restrict__ Bw, float* __restrict__ C,
             int M, int Nn, int K, int lda, int ldb, int ldc, int Hs,
             long aB, long aH, long bB, long bH, long cB, long cH, float alpha)
{
    int z = blockIdx.z;
    int zb = z / Hs, zh = z - zb * Hs;
    A  += zb * aB + zh * aH;
    Bw += zb * bB + zh * bH;
    C  += zb * cB + zh * cH;

    __shared__ float As[BK][BM + 1];
    __shared__ float Bs[BK][BN + 1];

    int m0 = blockIdx.y * BM;
    int n0 = blockIdx.x * BN;
    int tid = threadIdx.x;
    int tx = tid & 15, ty = tid >> 4;
    float acc[4][4] = {};

    for (int k0 = 0; k0 < K; k0 += BK) {
        #pragma unroll
        for (int i = 0; i < 4; i++) {
            int e  = tid + i * NTHR;        // 0..1023
            int kk = e & (BK - 1);
            int r  = e >> 4;                // 0..63
            int k  = k0 + kk;
            int m  = m0 + r;
            As[kk][r] = (m < M  && k < K) ? A [(long)m * lda + k] : 0.f;
            int n  = n0 + r;
            Bs[kk][r] = (n < Nn && k < K) ? Bw[(long)n * ldb + k] : 0.f;
        }
        __syncthreads();
        #pragma unroll
        for (int kk = 0; kk < BK; kk++) {
            float ra[4], rb[4];
            #pragma unroll
            for (int i = 0; i < 4; i++) ra[i] = As[kk][ty * 4 + i];
            #pragma unroll
            for (int j = 0; j < 4; j++) rb[j] = Bs[kk][tx * 4 + j];
            #pragma unroll
            for (int i = 0; i < 4; i++)
                #pragma unroll
                for (int j = 0; j < 4; j++)
                    acc[i][j] += ra[i] * rb[j];
        }
        __syncthreads();
    }
    #pragma unroll
    for (int i = 0; i < 4; i++) {
        int m = m0 + ty * 4 + i;
        if (m >= M) continue;
        #pragma unroll
        for (int j = 0; j < 4; j++) {
            int n = n0 + tx * 4 + j;
            if (n < Nn) C[(long)m * ldc + n] = alpha * acc[i][j];
        }
    }
}

// C[m,n] = alpha * sum_k A[k,m] * B[k,n]   (A row-major [K,M], B row-major [K,Nn])
__global__ __launch_bounds__(NTHR)
void gemm_tn(const float* __restrict__ A, const float* __restrict__ Bw, float* __restrict__ C,
             int M, int Nn, int K, int lda, int ldb, int ldc, int Hs,
             long aB, long aH, long bB, long bH, long cB, long cH, float alpha)
{
    int z = blockIdx.z;
    int zb = z / Hs, zh = z - zb * Hs;
    A  += zb * aB + zh * aH;
    Bw += zb * bB + zh * bH;
    C  += zb * cB + zh * cH;

    __shared__ float As[BK][BM + 1];
    __shared__ float Bs[BK][BN + 1];

    int m0 = blockIdx.y * BM;
    int n0 = blockIdx.x * BN;
    int tid = threadIdx.x;
    int tx = tid & 15, ty = tid >> 4;
    float acc[4][4] = {};

    for (int k0 = 0; k0 < K; k0 += BK) {
        #pragma unroll
        for (int i = 0; i < 4; i++) {
            int e  = tid + i * NTHR;
            int mm = e & (BM - 1);
            int kk = e >> 6;                // 0..15
            int k  = k0 + kk;
            int m  = m0 + mm;
            As[kk][mm] = (m < M  && k < K) ? A [(long)k * lda + m] : 0.f;
            int n  = n0 + mm;
            Bs[kk][mm] = (n < Nn && k < K) ? Bw[(long)k * ldb + n] : 0.f;
        }
        __syncthreads();
        #pragma unroll
        for (int kk = 0; kk < BK; kk++) {
            float ra[4], rb[4];
            #pragma unroll
            for (int i = 0; i < 4; i++) ra[i] = As[kk][ty * 4 + i];
            #pragma unroll
            for (int j = 0; j < 4; j++) rb[j] = Bs[kk][tx * 4 + j];
            #pragma unroll
            for (int i = 0; i < 4; i++)
                #pragma unroll
                for (int j = 0; j < 4; j++)
                    acc[i][j] += ra[i] * rb[j];
        }
        __syncthreads();
    }
    #pragma unroll
    for (int i = 0; i < 4; i++) {
        int m = m0 + ty * 4 + i;
        if (m >= M) continue;
        #pragma unroll
        for (int j = 0; j < 4; j++) {
            int n = n0 + tx * 4 + j;
            if (n < Nn) C[(long)m * ldc + n] = alpha * acc[i][j];
        }
    }
}

// heads[b,h,n,j] <- emb_all[b,n, seg(h,j)]
__global__ void gather_heads(const float* __restrict__ emb_all, float* __restrict__ heads)
{
    long idx = (long)blockIdx.x * blockDim.x + threadIdx.x;
    if (idx >= (long)SZ_BHND) return;
    int j = (int)(idx % Dc);
    long t = idx / Dc;
    int n = (int)(t % Nc); t /= Nc;
    int h = (int)(t % Hc);
    int b = (int)(t / Hc);
    int src;
    if      (j < 16)  src = 16  * h + j;
    else if (j < 48)  src = 64  + 32  * h + (j - 16);
    else if (j < 112) src = 192 + 64  * h + (j - 48);
    else              src = 448 + 128 * h + (j - 112);
    heads[idx] = emb_all[((long)b * Nc + n) * KVc + src];
}

// In-place: per (b,h) InstanceNorm over [d,240] (biased var, eps=1e-5) then softmax over k.
__global__ void norm_softmax(float* __restrict__ S, int d)
{
    float* p = S + (long)blockIdx.x * d * Dc;
    int count = d * Dc;
    float s = 0.f, ss = 0.f;
    for (int i = threadIdx.x; i < count; i += blockDim.x) {
        float v = p[i]; s += v; ss += v * v;
    }
    __shared__ float rs[8], rss[8], stats[2];
    #pragma unroll
    for (int o = 16; o; o >>= 1) {
        s  += __shfl_xor_sync(0xffffffffu, s,  o);
        ss += __shfl_xor_sync(0xffffffffu, ss, o);
    }
    int w = threadIdx.x >> 5, l = threadIdx.x & 31;
    if (l == 0) { rs[w] = s; rss[w] = ss; }
    __syncthreads();
    if (threadIdx.x == 0) {
        float a = 0.f, b2 = 0.f;
        for (int i = 0; i < 8; i++) { a += rs[i]; b2 += rss[i]; }
        float mean = a / count;
        float var  = b2 / count - mean * mean;
        stats[0] = mean;
        stats[1] = rsqrtf(var + 1e-5f);
    }
    __syncthreads();
    float mean = stats[0], istd = stats[1];

    for (int r = w; r < d; r += 8) {
        float* row = p + (long)r * Dc;
        float vals[8];
        float mx = -1e30f;
        #pragma unroll
        for (int t = 0; t < 8; t++) {
            int k = l + t * 32;
            float v = (k < Dc) ? (row[k] - mean) * istd : -1e30f;
            vals[t] = v;
            mx = fmaxf(mx, v);
        }
        #pragma unroll
        for (int o = 16; o; o >>= 1) mx = fmaxf(mx, __shfl_xor_sync(0xffffffffu, mx, o));
        float se = 0.f;
        #pragma unroll
        for (int t = 0; t < 8; t++) {
            int k = l + t * 32;
            float e = (k < Dc) ? __expf(vals[t] - mx) : 0.f;
            vals[t] = e; se += e;
        }
        #pragma unroll
        for (int o = 16; o; o >>= 1) se += __shfl_xor_sync(0xffffffffu, se, o);
        float inv = 1.f / se;
        #pragma unroll
        for (int t = 0; t < 8; t++) {
            int k = l + t * 32;
            if (k < Dc) row[k] = vals[t] * inv;
        }
    }
}

// ctxT[b,n, dd*H+h] <- ctx[b,h,dd,n]
__global__ void transpose_ctx(const float* __restrict__ ctx, float* __restrict__ out, int d, int CH)
{
    long total = (long)Bc * Nc * CH;
    long idx = (long)blockIdx.x * blockDim.x + threadIdx.x;
    if (idx >= total) return;
    int c = (int)(idx % CH);
    long t = idx / CH;
    int n = (int)(t % Nc);
    int b = (int)(t / Nc);
    int h  = c % Hc;
    int dd = c / Hc;
    out[idx] = ctx[(((long)b * Hc + h) * d + dd) * Nc + n];
}

extern "C" void kernel_launch(void* const* d_in, const int* in_sizes, int n_in,
                              void* d_out, int out_size)
{
    const float* emb[4]  = { (const float*)d_in[0], (const float*)d_in[1],
                             (const float*)d_in[2], (const float*)d_in[3] };
    const float* emb_all = (const float*)d_in[4];
    const float* Wq[4]   = { (const float*)d_in[5], (const float*)d_in[6],
                             (const float*)d_in[7], (const float*)d_in[8] };
    const float* Wk      = (const float*)d_in[9];
    const float* Wv      = (const float*)d_in[10];
    const float* Wo[4]   = { (const float*)d_in[11], (const float*)d_in[12],
                             (const float*)d_in[13], (const float*)d_in[14] };
    float* out = (float*)d_out;

    float *pHeads, *pKh, *pVh, *pQh, *pS, *pCtx, *pCtxT;
    cudaGetSymbolAddress((void**)&pHeads, g_heads);
    cudaGetSymbolAddress((void**)&pKh,    g_Kh);
    cudaGetSymbolAddress((void**)&pVh,    g_Vh);
    cudaGetSymbolAddress((void**)&pQh,    g_Qh);
    cudaGetSymbolAddress((void**)&pS,     g_S);
    cudaGetSymbolAddress((void**)&pCtx,   g_ctx);
    cudaGetSymbolAddress((void**)&pCtxT,  g_ctxT);

    const int dArr[4]  = {16, 32, 64, 128};
    const int chArr[4] = {64, 128, 256, 512};
    const int dcum[4]  = {0, 16, 48, 112};
    const int chcum[4] = {0, 64, 192, 448};

    dim3 blk(NTHR);

    // 1) gather heads
    {
        long total = (long)SZ_BHND;
        gather_heads<<<(unsigned)((total + 255) / 256), 256>>>(emb_all, pHeads);
    }

    // 2) Kh = heads @ Wk^T, Vh = heads @ Wv^T  (M = B*H*N = 65536, Nn = K = 240)
    {
        dim3 grid((Dc + BN - 1) / BN, (Bc * Hc * Nc + BM - 1) / BM, 1);
        gemm_nt<<<grid, blk>>>(pHeads, Wk, pKh, Bc * Hc * Nc, Dc, Dc, Dc, Dc, Dc,
                               1, 0, 0, 0, 0, 0, 0, 1.f);
        gemm_nt<<<grid, blk>>>(pHeads, Wv, pVh, Bc * Hc * Nc, Dc, Dc, Dc, Dc, Dc,
                               1, 0, 0, 0, 0, 0, 0, 1.f);
    }

    const float alpha = 1.f / sqrtf((float)KVc);

    for (int sc = 0; sc < 4; sc++) {
        int d = dArr[sc], CH = chArr[sc];
        float* Qh   = pQh   + (long)Bc * Hc * Nc * dcum[sc];   // [B,H,N,d]
        float* Ss   = pS    + (long)Bc * Hc * Dc * dcum[sc];   // [B,H,d,240]
        float* ctx  = pCtx  + (long)Bc * Hc * Nc * dcum[sc];   // [B,H,d,N]  (B*H*N*dcum == B*H*dcum*N)
        float* ctxT = pCtxT + (long)Bc * Nc * chcum[sc];       // [B,N,CH]
        float* Osc  = out   + (long)Bc * Nc * chcum[sc];

        // 3) Qh[b,h,n,e] = sum_d emb[b,n,h*d+d'] * Wq[h,e,d']  — batched over z=(b,h)
        {
            dim3 grid((d + BN - 1) / BN, (Nc + BM - 1) / BM, Bc * Hc);
            gemm_nt<<<grid, blk>>>(emb[sc], Wq[sc], Qh,
                                   Nc, d, d, CH, d, d,
                                   Hc,
                                   (long)Nc * CH, (long)d,       // A: b*N*CH + h*d
                                   0,             (long)d * d,   // B: h*d*d
                                   (long)Hc * Nc * d, (long)Nc * d, // C: (b*H+h)*N*d
                                   1.f);
        }
        // 4) scores[b,h,dd,k] = alpha * sum_n Qh[n,dd] * Kh[n,k]   (TN GEMM per (b,h))
        {
            dim3 grid((Dc + BN - 1) / BN, (d + BM - 1) / BM, Bc * Hc);
            gemm_tn<<<grid, blk>>>(Qh, pKh, Ss,
                                   d, Dc, Nc, d, Dc, Dc,
                                   1,
                                   (long)Nc * d, 0,
                                   (long)Nc * Dc, 0,
                                   (long)d * Dc, 0,
                                   alpha);
        }
        // 5) instance-norm + softmax (in place)
        norm_softmax<<<Bc * Hc, 256>>>(Ss, d);

        // 6) ctx[b,h,dd,n] = sum_k probs[dd,k] * Vh[n,k]   (NT GEMM per (b,h))
        {
            dim3 grid((Nc + BN - 1) / BN, (d + BM - 1) / BM, Bc * Hc);
            gemm_nt<<<grid, blk>>>(Ss, pVh, ctx,
                                   d, Nc, Dc, Dc, Dc, Nc,
                                   1,
                                   (long)d * Dc, 0,
                                   (long)Nc * Dc, 0,
                                   (long)d * Nc, 0,
                                   1.f);
        }
        // 7) ctx -> [B,N,CH] with c = dd*H + h
        {
            long total = (long)Bc * Nc * CH;
            transpose_ctx<<<(unsigned)((total + 255) / 256), 256>>>(ctx, ctxT, d, CH);
        }
        // 8) O = ctxT @ Wo^T
        {
            dim3 grid((CH + BN - 1) / BN, (Bc * Nc + BM - 1) / BM, 1);
            gemm_nt<<<grid, blk>>>(ctxT, Wo[sc], Osc,
                                   Bc * Nc, CH, CH, CH, CH, CH,
                                   1, 0, 0, 0, 0, 0, 0, 1.f);
        }
    }
}

// round 2
// speedup vs baseline: 2.5567x; 2.5567x over previous
#include <cuda_runtime.h>
#include <math.h>
#include <stdint.h>

// Problem constants
#define Bc 16
#define Nc 1024
#define Hc 4
#define KVc 960
#define Dc 240            // KV/4, per-head K/V feature dim

#define SZ_BHND (Bc*Hc*Nc*Dc)   // 15,728,640

// ---------------- scratch (static device globals; no allocation) ----------
__device__ float g_heads[SZ_BHND];          // [B,H,N,240]
__device__ float g_Kh   [SZ_BHND];          // [B,H,N,240]
__device__ float g_Vh   [SZ_BHND];          // [B,H,N,240]
__device__ float g_Qh   [SZ_BHND];          // per-scale blocks [B,H,d,N]  (Q TRANSPOSED)
__device__ float g_S    [Bc*Hc*Dc*Dc];      // per-scale blocks [B,H,d,240]
__device__ float g_ctx  [SZ_BHND];          // per-scale blocks [B,H,d,N]
__device__ float g_ctxT [Bc*Nc*KVc];        // per-scale blocks [B,N,CH]

// ---------------- tf32 tensor-core GEMM ----------------
__device__ __forceinline__ void cpasync16(uint32_t dst, const void* src, int sz) {
    asm volatile("cp.async.ca.shared.global [%0], [%1], 16, %2;\n"
                 :: "r"(dst), "l"(src), "r"(sz));
}
__device__ __forceinline__ uint32_t f2tf(float f) {
    uint32_t r; asm("cvt.rna.tf32.f32 %0, %1;" : "=r"(r) : "f"(f)); return r;
}

// NN=false: C[m,n] = alpha * sum_k A[m,k]*B[n,k]   (A [M,K] lda, B [Nn,K] ldb)
// NN=true : C[m,n] = alpha * sum_k A[m,k]*B[k,n]   (A [M,K] lda, B [K,Nn] ldb)
// Requirements: K % 8 == 0, lda/ldb/ldc % 4 == 0, all base offsets 16B aligned,
//               Nn even (float2 epilogue).
// batched via blockIdx.z; offsets = (z/Hs)*xB + (z%Hs)*xH
template<bool NN>
__global__ __launch_bounds__(128)
void gemm_tc(const float* __restrict__ A, const float* __restrict__ B, float* __restrict__ C,
             int M, int Nn, int K, int lda, int ldb, int ldc, int Hs,
             long aB, long aH, long bB, long bH, long cB, long cH, float alpha)
{
    int z = blockIdx.z, zb = z / Hs, zh = z - zb * Hs;
    A += zb * aB + zh * aH;
    B += zb * bB + zh * bH;
    C += zb * cB + zh * cH;

    const int m0 = blockIdx.y * 64, n0 = blockIdx.x * 64;
    const int tid = threadIdx.x, lane = tid & 31, warp = tid >> 5;
    const int wm = warp >> 1, wn = warp & 1;      // 2x2 warps, 32x32 per warp
    const int g = lane >> 2, c4 = lane & 3;

    __shared__ float sA[2][64 * 12];              // [m][k] padded to 12
    __shared__ float sB[2][768];                  // NT: [n][k] pad12 ; NN: [k][n] pad72

    float acc[2][4][4];
    #pragma unroll
    for (int i = 0; i < 2; i++)
        #pragma unroll
        for (int j = 0; j < 4; j++)
            #pragma unroll
            for (int r = 0; r < 4; r++) acc[i][j][r] = 0.f;

    const int ar = tid >> 1, ah = (tid & 1) * 4;  // A/B-NT loader: row, 16B-half
    const int bk = tid >> 4, bn = (tid & 15) * 4; // B-NN loader: k row, n col

    const int KT = K >> 3;

    // prefetch stage 0
    cpasync16((uint32_t)__cvta_generic_to_shared(&sA[0][ar * 12 + ah]),
              A + (long)(m0 + ar) * lda + ah, (m0 + ar < M) ? 16 : 0);
    if (NN)
        cpasync16((uint32_t)__cvta_generic_to_shared(&sB[0][bk * 72 + bn]),
                  B + (long)bk * ldb + n0 + bn, (n0 + bn < Nn) ? 16 : 0);
    else
        cpasync16((uint32_t)__cvta_generic_to_shared(&sB[0][ar * 12 + ah]),
                  B + (long)(n0 + ar) * ldb + ah, (n0 + ar < Nn) ? 16 : 0);
    asm volatile("cp.async.commit_group;\n");

    for (int kt = 0; kt < KT; kt++) {
        int cur = kt & 1;
        if (kt + 1 < KT) {
            int k0 = (kt + 1) << 3;
            cpasync16((uint32_t)__cvta_generic_to_shared(&sA[cur ^ 1][ar * 12 + ah]),
                      A + (long)(m0 + ar) * lda + k0 + ah, (m0 + ar < M) ? 16 : 0);
            if (NN)
                cpasync16((uint32_t)__cvta_generic_to_shared(&sB[cur ^ 1][bk * 72 + bn]),
                          B + (long)(k0 + bk) * ldb + n0 + bn, (n0 + bn < Nn) ? 16 : 0);
            else
                cpasync16((uint32_t)__cvta_generic_to_shared(&sB[cur ^ 1][ar * 12 + ah]),
                          B + (long)(n0 + ar) * ldb + k0 + ah, (n0 + ar < Nn) ? 16 : 0);
        }
        asm volatile("cp.async.commit_group;\n");
        asm volatile("cp.async.wait_group 1;\n");
        __syncthreads();

        const float* a_s = sA[cur];
        const float* b_s = sB[cur];
        uint32_t af[2][4], bf[4][2];
        #pragma unroll
        for (int fm = 0; fm < 2; fm++) {
            int mb = wm * 32 + fm * 16;
            af[fm][0] = f2tf(a_s[(mb + g) * 12 + c4]);
            af[fm][1] = f2tf(a_s[(mb + g + 8) * 12 + c4]);
            af[fm][2] = f2tf(a_s[(mb + g) * 12 + c4 + 4]);
            af[fm][3] = f2tf(a_s[(mb + g + 8) * 12 + c4 + 4]);
        }
        #pragma unroll
        for (int fn = 0; fn < 4; fn++) {
            int nb = wn * 32 + fn * 8 + g;
            if (NN) {
                bf[fn][0] = f2tf(b_s[c4 * 72 + nb]);
                bf[fn][1] = f2tf(b_s[(c4 + 4) * 72 + nb]);
            } else {
                bf[fn][0] = f2tf(b_s[nb * 12 + c4]);
                bf[fn][1] = f2tf(b_s[nb * 12 + c4 + 4]);
            }
        }
        #pragma unroll
        for (int fm = 0; fm < 2; fm++)
            #pragma unroll
            for (int fn = 0; fn < 4; fn++)
                asm volatile(
                    "mma.sync.aligned.m16n8k8.row.col.f32.tf32.tf32.f32 "
                    "{%0,%1,%2,%3}, {%4,%5,%6,%7}, {%8,%9}, {%0,%1,%2,%3};\n"
                    : "+f"(acc[fm][fn][0]), "+f"(acc[fm][fn][1]),
                      "+f"(acc[fm][fn][2]), "+f"(acc[fm][fn][3])
                    : "r"(af[fm][0]), "r"(af[fm][1]), "r"(af[fm][2]), "r"(af[fm][3]),
                      "r"(bf[fn][0]), "r"(bf[fn][1]));
        __syncthreads();
    }

    // epilogue
    #pragma unroll
    for (int fm = 0; fm < 2; fm++) {
        int row = m0 + wm * 32 + fm * 16 + g;
        #pragma unroll
        for (int fn = 0; fn < 4; fn++) {
            int col = n0 + wn * 32 + fn * 8 + c4 * 2;
            if (col < Nn) {
                if (row < M) {
                    float2 v = make_float2(alpha * acc[fm][fn][0], alpha * acc[fm][fn][1]);
                    *(float2*)(C + (long)row * ldc + col) = v;
                }
                if (row + 8 < M) {
                    float2 v = make_float2(alpha * acc[fm][fn][2], alpha * acc[fm][fn][3]);
                    *(float2*)(C + (long)(row + 8) * ldc + col) = v;
                }
            }
        }
    }
}

// heads[b,h,n,j] <- emb_all[b,n, seg(h,j)]
__global__ void gather_heads(const float* __restrict__ emb_all, float* __restrict__ heads)
{
    long idx = (long)blockIdx.x * blockDim.x + threadIdx.x;
    if (idx >= (long)SZ_BHND) return;
    int j = (int)(idx % Dc);
    long t = idx / Dc;
    int n = (int)(t % Nc); t /= Nc;
    int h = (int)(t % Hc);
    int b = (int)(t / Hc);
    int src;
    if      (j < 16)  src = 16  * h + j;
    else if (j < 48)  src = 64  + 32  * h + (j - 16);
    else if (j < 112) src = 192 + 64  * h + (j - 48);
    else              src = 448 + 128 * h + (j - 112);
    heads[idx] = emb_all[((long)b * Nc + n) * KVc + src];
}

// In-place: per (b,h) InstanceNorm over [d,240] (biased var, eps=1e-5) then softmax over k.
__global__ void norm_softmax(float* __restrict__ S, int d)
{
    float* p = S + (long)blockIdx.x * d * Dc;
    int count = d * Dc;
    float s = 0.f, ss = 0.f;
    for (int i = threadIdx.x; i < count; i += blockDim.x) {
        float v = p[i]; s += v; ss += v * v;
    }
    __shared__ float rs[8], rss[8], stats[2];
    #pragma unroll
    for (int o = 16; o; o >>= 1) {
        s  += __shfl_xor_sync(0xffffffffu, s,  o);
        ss += __shfl_xor_sync(0xffffffffu, ss, o);
    }
    int w = threadIdx.x >> 5, l = threadIdx.x & 31;
    if (l == 0) { rs[w] = s; rss[w] = ss; }
    __syncthreads();
    if (threadIdx.x == 0) {
        float a = 0.f, b2 = 0.f;
        for (int i = 0; i < 8; i++) { a += rs[i]; b2 += rss[i]; }
        float mean = a / count;
        float var  = b2 / count - mean * mean;
        stats[0] = mean;
        stats[1] = rsqrtf(var + 1e-5f);
    }
    __syncthreads();
    float mean = stats[0], istd = stats[1];

    for (int r = w; r < d; r += 8) {
        float* row = p + (long)r * Dc;
        float vals[8];
        float mx = -1e30f;
        #pragma unroll
        for (int t = 0; t < 8; t++) {
            int k = l + t * 32;
            float v = (k < Dc) ? (row[k] - mean) * istd : -1e30f;
            vals[t] = v;
            mx = fmaxf(mx, v);
        }
        #pragma unroll
        for (int o = 16; o; o >>= 1) mx = fmaxf(mx, __shfl_xor_sync(0xffffffffu, mx, o));
        float se = 0.f;
        #pragma unroll
        for (int t = 0; t < 8; t++) {
            int k = l + t * 32;
            float e = (k < Dc) ? __expf(vals[t] - mx) : 0.f;
            vals[t] = e; se += e;
        }
        #pragma unroll
        for (int o = 16; o; o >>= 1) se += __shfl_xor_sync(0xffffffffu, se, o);
        float inv = 1.f / se;
        #pragma unroll
        for (int t = 0; t < 8; t++) {
            int k = l + t * 32;
            if (k < Dc) row[k] = vals[t] * inv;
        }
    }
}

// ctxT[b,n, dd*H+h] <- ctx[b,h,dd,n]
__global__ void transpose_ctx(const float* __restrict__ ctx, float* __restrict__ out, int d, int CH)
{
    long total = (long)Bc * Nc * CH;
    long idx = (long)blockIdx.x * blockDim.x + threadIdx.x;
    if (idx >= total) return;
    int c = (int)(idx % CH);
    long t = idx / CH;
    int n = (int)(t % Nc);
    int b = (int)(t / Nc);
    int h  = c % Hc;
    int dd = c / Hc;
    out[idx] = ctx[(((long)b * Hc + h) * d + dd) * Nc + n];
}

extern "C" void kernel_launch(void* const* d_in, const int* in_sizes, int n_in,
                              void* d_out, int out_size)
{
    const float* emb[4]  = { (const float*)d_in[0], (const float*)d_in[1],
                             (const float*)d_in[2], (const float*)d_in[3] };
    const float* emb_all = (const float*)d_in[4];
    const float* Wq[4]   = { (const float*)d_in[5], (const float*)d_in[6],
                             (const float*)d_in[7], (const float*)d_in[8] };
    const float* Wk      = (const float*)d_in[9];
    const float* Wv      = (const float*)d_in[10];
    const float* Wo[4]   = { (const float*)d_in[11], (const float*)d_in[12],
                             (const float*)d_in[13], (const float*)d_in[14] };
    float* out = (float*)d_out;

    float *pHeads, *pKh, *pVh, *pQh, *pS, *pCtx, *pCtxT;
    cudaGetSymbolAddress((void**)&pHeads, g_heads);
    cudaGetSymbolAddress((void**)&pKh,    g_Kh);
    cudaGetSymbolAddress((void**)&pVh,    g_Vh);
    cudaGetSymbolAddress((void**)&pQh,    g_Qh);
    cudaGetSymbolAddress((void**)&pS,     g_S);
    cudaGetSymbolAddress((void**)&pCtx,   g_ctx);
    cudaGetSymbolAddress((void**)&pCtxT,  g_ctxT);

    const int dArr[4]  = {16, 32, 64, 128};
    const int chArr[4] = {64, 128, 256, 512};
    const int dcum[4]  = {0, 16, 48, 112};
    const int chcum[4] = {0, 64, 192, 448};

    // 1) gather heads
    {
        long total = (long)SZ_BHND;
        gather_heads<<<(unsigned)((total + 255) / 256), 256>>>(emb_all, pHeads);
    }

    // 2) Kh = heads @ Wk^T, Vh = heads @ Wv^T   (NT, M=65536, Nn=K=240)
    {
        dim3 grid(4, 1024, 1);
        gemm_tc<false><<<grid, 128>>>(pHeads, Wk, pKh, Bc * Hc * Nc, Dc, Dc,
                                      Dc, Dc, Dc, 1, 0, 0, 0, 0, 0, 0, 1.f);
        gemm_tc<false><<<grid, 128>>>(pHeads, Wv, pVh, Bc * Hc * Nc, Dc, Dc,
                                      Dc, Dc, Dc, 1, 0, 0, 0, 0, 0, 0, 1.f);
    }

    const float alpha = 1.f / sqrtf((float)KVc);

    for (int sc = 0; sc < 4; sc++) {
        int d = dArr[sc], CH = chArr[sc];
        float* Qh   = pQh   + (long)Bc * Hc * Nc * dcum[sc];   // [B,H,d,N] (transposed)
        float* Ss   = pS    + (long)Bc * Hc * Dc * dcum[sc];   // [B,H,d,240]
        float* ctx  = pCtx  + (long)Bc * Hc * Nc * dcum[sc];   // [B,H,d,N]
        float* ctxT = pCtxT + (long)Bc * Nc * chcum[sc];       // [B,N,CH]
        float* Osc  = out   + (long)Bc * Nc * chcum[sc];

        // 3) QhT[b,h][e,n] = sum_{d'} Wq[h][e,d'] * emb[b][n][h*d + d']  (NT per (b,h))
        {
            dim3 grid(Nc / 64, (d + 63) / 64, Bc * Hc);
            gemm_tc<false><<<grid, 128>>>(Wq[sc], emb[sc], Qh,
                                          d, Nc, d, d, CH, Nc,
                                          Hc,
                                          0,              (long)d * d,
                                          (long)Nc * CH,  (long)d,
                                          (long)Hc * Nc * d, (long)Nc * d,
                                          1.f);
        }
        // 4) scores[b,h][dd,k] = alpha * sum_n QhT[dd,n] * Kh[n,k]   (NN per (b,h))
        {
            dim3 grid((Dc + 63) / 64, (d + 63) / 64, Bc * Hc);
            gemm_tc<true><<<grid, 128>>>(Qh, pKh, Ss,
                                         d, Dc, Nc, Nc, Dc, Dc,
                                         1,
                                         (long)Nc * d,  0,
                                         (long)Nc * Dc, 0,
                                         (long)d * Dc,  0,
                                         alpha);
        }
        // 5) instance-norm + softmax (in place)
        norm_softmax<<<Bc * Hc, 256>>>(Ss, d);

        // 6) ctx[b,h][dd,n] = sum_k probs[dd,k] * Vh[n,k]   (NT per (b,h))
        {
            dim3 grid(Nc / 64, (d + 63) / 64, Bc * Hc);
            gemm_tc<false><<<grid, 128>>>(Ss, pVh, ctx,
                                          d, Nc, Dc, Dc, Dc, Nc,
                                          1,
                                          (long)d * Dc,  0,
                                          (long)Nc * Dc, 0,
                                          (long)d * Nc,  0,
                                          1.f);
        }
        // 7) ctx -> [B,N,CH] with c = dd*H + h
        {
            long total = (long)Bc * Nc * CH;
            transpose_ctx<<<(unsigned)((total + 255) / 256), 256>>>(ctx, ctxT, d, CH);
        }
        // 8) O = ctxT @ Wo^T   (NT, M=16384)
        {
            dim3 grid(CH / 64, Bc * Nc / 64, 1);
            gemm_tc<false><<<grid, 128>>>(ctxT, Wo[sc], Osc,
                                          Bc * Nc, CH, CH, CH, CH, CH,
                                          1, 0, 0, 0, 0, 0, 0, 1.f);
        }
    }
}

// round 4
// speedup vs baseline: 3.4613x; 1.3538x over previous
#include <cuda_runtime.h>
#include <math.h>
#include <stdint.h>

// Problem constants
#define Bc 16
#define Nc 1024
#define Hc 4
#define KVc 960
#define Dc 240            // KV/4, per-head K/V feature dim

#define SZ_BHND (Bc*Hc*Nc*Dc)   // 15,728,640

// ---------------- scratch (static device globals; no allocation) ----------
__device__ float g_Kh  [SZ_BHND];           // [B,H,N,240]
__device__ float g_Vh  [SZ_BHND];           // [B,H,N,240]
__device__ float g_Qh  [SZ_BHND];           // per-scale blocks [B,H,d,N]  (Q transposed)
__device__ float g_S   [Bc*Hc*Dc*Dc];       // per-scale blocks [B,H,d,240]
__device__ float g_ctxT[Bc*Nc*KVc];         // per-scale blocks [B,N,CH]

// ---------------- helpers ----------------
__device__ __forceinline__ void cpasync16(uint32_t dst, const void* src, int sz) {
    asm volatile("cp.async.ca.shared.global [%0], [%1], 16, %2;\n"
                 :: "r"(dst), "l"(src), "r"(sz));
}
__device__ __forceinline__ uint32_t f2tf(float f) {
    uint32_t r; asm("cvt.rna.tf32.f32 %0, %1;" : "=r"(r) : "f"(f)); return r;
}
__device__ __forceinline__ void mma_tf32(float* acc, const uint32_t* a, const uint32_t* b) {
    asm volatile("mma.sync.aligned.m16n8k8.row.col.f32.tf32.tf32.f32 "
                 "{%0,%1,%2,%3}, {%4,%5,%6,%7}, {%8,%9}, {%0,%1,%2,%3};\n"
                 : "+f"(acc[0]), "+f"(acc[1]), "+f"(acc[2]), "+f"(acc[3])
                 : "r"(a[0]), "r"(a[1]), "r"(a[2]), "r"(a[3]), "r"(b[0]), "r"(b[1]));
}

// =======================================================================
// 64x64 tile, 128 threads, BK=16, tf32 mma
// NN=false: C[m,n] = alpha * sum_k A[m,k]*B[n,k]
// NN=true : C[m,n] = alpha * sum_k A[m,k]*B[k,n]
// SC=true : strided C store: C[r*ldc + col*ldcC] (scalar)
// Requirements: K%16==0, lda/ldb%4==0, Nn%4==0, bases 16B aligned.
// =======================================================================
template<bool NN, bool SC>
__global__ __launch_bounds__(128)
void gemm64(const float* __restrict__ A, const float* __restrict__ B, float* __restrict__ C,
            int M, int Nn, int K, int lda, int ldb, int ldc, int ldcC, int Hs,
            long aB, long aH, long bB, long bH, long cB, long cH, float alpha)
{
    int z = blockIdx.z, zb = z / Hs, zh = z - zb * Hs;
    A += zb * aB + zh * aH;
    B += zb * bB + zh * bH;
    C += zb * cB + zh * cH;

    const int m0 = blockIdx.y * 64, n0 = blockIdx.x * 64;
    const int tid = threadIdx.x, lane = tid & 31, warp = tid >> 5;
    const int wm = warp >> 1, wn = warp & 1;
    const int g = lane >> 2, c4 = lane & 3;

    __shared__ float sA[2][64 * 20];
    __shared__ float sB[2][NN ? 16 * 72 : 64 * 20];

    float acc[2][4][4] = {};

    const int ar = tid >> 1, ac = (tid & 1) * 8;
    const int br = tid >> 3, bc = (tid & 7) * 8;

    auto fill = [&](int s, int k0) {
        const float* ap = A + (long)(m0 + ar) * lda + k0 + ac;
        int sa = (m0 + ar < M) ? 16 : 0;
        cpasync16((uint32_t)__cvta_generic_to_shared(&sA[s][ar * 20 + ac]),     ap,     sa);
        cpasync16((uint32_t)__cvta_generic_to_shared(&sA[s][ar * 20 + ac + 4]), ap + 4, sa);
        if (NN) {
            const float* bp = B + (long)(k0 + br) * ldb + n0 + bc;
            cpasync16((uint32_t)__cvta_generic_to_shared(&sB[s][br * 72 + bc]),     bp,     (n0 + bc     < Nn) ? 16 : 0);
            cpasync16((uint32_t)__cvta_generic_to_shared(&sB[s][br * 72 + bc + 4]), bp + 4, (n0 + bc + 4 < Nn) ? 16 : 0);
        } else {
            const float* bp = B + (long)(n0 + ar) * ldb + k0 + ac;
            int sb = (n0 + ar < Nn) ? 16 : 0;
            cpasync16((uint32_t)__cvta_generic_to_shared(&sB[s][ar * 20 + ac]),     bp,     sb);
            cpasync16((uint32_t)__cvta_generic_to_shared(&sB[s][ar * 20 + ac + 4]), bp + 4, sb);
        }
    };

    const int KT = K >> 4;
    fill(0, 0);
    asm volatile("cp.async.commit_group;\n");
    for (int kt = 0; kt < KT; kt++) {
        int cur = kt & 1;
        if (kt + 1 < KT) fill(cur ^ 1, (kt + 1) << 4);
        asm volatile("cp.async.commit_group;\n");
        asm volatile("cp.async.wait_group 1;\n");
        __syncthreads();
        const float* a_s = sA[cur];
        const float* b_s = sB[cur];
        #pragma unroll
        for (int ks = 0; ks < 16; ks += 8) {
            uint32_t af[2][4], bf[4][2];
            #pragma unroll
            for (int fm = 0; fm < 2; fm++) {
                int mb = wm * 32 + fm * 16;
                af[fm][0] = f2tf(a_s[(mb + g    ) * 20 + ks + c4]);
                af[fm][1] = f2tf(a_s[(mb + g + 8) * 20 + ks + c4]);
                af[fm][2] = f2tf(a_s[(mb + g    ) * 20 + ks + c4 + 4]);
                af[fm][3] = f2tf(a_s[(mb + g + 8) * 20 + ks + c4 + 4]);
            }
            #pragma unroll
            for (int fn = 0; fn < 4; fn++) {
                int nb = wn * 32 + fn * 8 + g;
                if (NN) {
                    bf[fn][0] = f2tf(b_s[(ks + c4    ) * 72 + nb]);
                    bf[fn][1] = f2tf(b_s[(ks + c4 + 4) * 72 + nb]);
                } else {
                    bf[fn][0] = f2tf(b_s[nb * 20 + ks + c4]);
                    bf[fn][1] = f2tf(b_s[nb * 20 + ks + c4 + 4]);
                }
            }
            #pragma unroll
            for (int fm = 0; fm < 2; fm++)
                #pragma unroll
                for (int fn = 0; fn < 4; fn++)
                    mma_tf32(acc[fm][fn], af[fm], bf[fn]);
        }
        __syncthreads();
    }

    #pragma unroll
    for (int fm = 0; fm < 2; fm++) {
        int row0 = m0 + wm * 32 + fm * 16 + g;
        #pragma unroll
        for (int half = 0; half < 2; half++) {
            int r = row0 + half * 8;
            if (r >= M) continue;
            #pragma unroll
            for (int fn = 0; fn < 4; fn++) {
                int col = n0 + wn * 32 + fn * 8 + c4 * 2;
                if (col >= Nn) continue;
                float v0 = alpha * acc[fm][fn][half * 2 + 0];
                float v1 = alpha * acc[fm][fn][half * 2 + 1];
                if (SC) {
                    C[(long)r * ldc + (long)col * ldcC] = v0;
                    C[(long)r * ldc + (long)(col + 1) * ldcC] = v1;
                } else {
                    *(float2*)(C + (long)r * ldc + col) = make_float2(v0, v1);
                }
            }
        }
    }
}

// =======================================================================
// 128x128 tile, 256 threads, BK=16 — plain NT: C = alpha*A*B^T
// =======================================================================
__global__ __launch_bounds__(256)
void gemm128(const float* __restrict__ A, const float* __restrict__ B, float* __restrict__ C,
             int M, int Nn, int K, int lda, int ldb, int ldc, float alpha)
{
    const int m0 = blockIdx.y * 128, n0 = blockIdx.x * 128;
    const int tid = threadIdx.x, lane = tid & 31, warp = tid >> 5;
    const int wm = warp >> 1, wn = warp & 1;   // 4x2 warps: warp tile 32x64
    const int g = lane >> 2, c4 = lane & 3;

    __shared__ float sA[2][128 * 20];
    __shared__ float sB[2][128 * 20];

    float acc[2][8][4] = {};

    const int ar = tid >> 1, ac = (tid & 1) * 8;

    auto fill = [&](int s, int k0) {
        const float* ap = A + (long)(m0 + ar) * lda + k0 + ac;
        int sa = (m0 + ar < M) ? 16 : 0;
        cpasync16((uint32_t)__cvta_generic_to_shared(&sA[s][ar * 20 + ac]),     ap,     sa);
        cpasync16((uint32_t)__cvta_generic_to_shared(&sA[s][ar * 20 + ac + 4]), ap + 4, sa);
        const float* bp = B + (long)(n0 + ar) * ldb + k0 + ac;
        int sb = (n0 + ar < Nn) ? 16 : 0;
        cpasync16((uint32_t)__cvta_generic_to_shared(&sB[s][ar * 20 + ac]),     bp,     sb);
        cpasync16((uint32_t)__cvta_generic_to_shared(&sB[s][ar * 20 + ac + 4]), bp + 4, sb);
    };

    const int KT = K >> 4;
    fill(0, 0);
    asm volatile("cp.async.commit_group;\n");
    for (int kt = 0; kt < KT; kt++) {
        int cur = kt & 1;
        if (kt + 1 < KT) fill(cur ^ 1, (kt + 1) << 4);
        asm volatile("cp.async.commit_group;\n");
        asm volatile("cp.async.wait_group 1;\n");
        __syncthreads();
        const float* a_s = sA[cur];
        const float* b_s = sB[cur];
        #pragma unroll
        for (int ks = 0; ks < 16; ks += 8) {
            uint32_t af[2][4], bf[8][2];
            #pragma unroll
            for (int fm = 0; fm < 2; fm++) {
                int mb = wm * 32 + fm * 16;
                af[fm][0] = f2tf(a_s[(mb + g    ) * 20 + ks + c4]);
                af[fm][1] = f2tf(a_s[(mb + g + 8) * 20 + ks + c4]);
                af[fm][2] = f2tf(a_s[(mb + g    ) * 20 + ks + c4 + 4]);
                af[fm][3] = f2tf(a_s[(mb + g + 8) * 20 + ks + c4 + 4]);
            }
            #pragma unroll
            for (int fn = 0; fn < 8; fn++) {
                int nb = wn * 64 + fn * 8 + g;
                bf[fn][0] = f2tf(b_s[nb * 20 + ks + c4]);
                bf[fn][1] = f2tf(b_s[nb * 20 + ks + c4 + 4]);
            }
            #pragma unroll
            for (int fm = 0; fm < 2; fm++)
                #pragma unroll
                for (int fn = 0; fn < 8; fn++)
                    mma_tf32(acc[fm][fn], af[fm], bf[fn]);
        }
        __syncthreads();
    }

    #pragma unroll
    for (int fm = 0; fm < 2; fm++) {
        int row0 = m0 + wm * 32 + fm * 16 + g;
        #pragma unroll
        for (int half = 0; half < 2; half++) {
            int r = row0 + half * 8;
            if (r >= M) continue;
            #pragma unroll
            for (int fn = 0; fn < 8; fn++) {
                int col = n0 + wn * 64 + fn * 8 + c4 * 2;
                if (col >= Nn) continue;
                *(float2*)(C + (long)r * ldc + col) =
                    make_float2(alpha * acc[fm][fn][half * 2], alpha * acc[fm][fn][half * 2 + 1]);
            }
        }
    }
}

// =======================================================================
// Fused gather + K/V projection. 128x128 tile.
//   A[m=(b,h,n), j] = emb_all[b, n, seg(h,j)]   (gathered on the fly)
//   B = [Wk ; Wv] stacked (480 rows of 240)
//   C col<240 -> Kh[m,col], col<480 -> Vh[m,col-240]
// =======================================================================
__global__ __launch_bounds__(256)
void kvproj(const float* __restrict__ emb_all, const float* __restrict__ Wk,
            const float* __restrict__ Wv, float* __restrict__ Kh, float* __restrict__ Vh)
{
    const int m0 = blockIdx.y * 128, n0 = blockIdx.x * 128;
    const int tid = threadIdx.x, lane = tid & 31, warp = tid >> 5;
    const int wm = warp >> 1, wn = warp & 1;
    const int g = lane >> 2, c4 = lane & 3;

    __shared__ float sA[2][128 * 20];
    __shared__ float sB[2][128 * 20];

    float acc[2][8][4] = {};

    const int ar = tid >> 1, ac = (tid & 1) * 8;

    // gather base for this thread's A row
    int m = m0 + ar;                 // always < 65536
    int b = m >> 12, h = (m >> 10) & 3, n = m & 1023;
    const float* abase = emb_all + ((long)(b * Nc + n)) * KVc;

    // B row source
    int r = n0 + ar;
    const float* bbase;
    int bsz;
    if (r < 240)      { bbase = Wk + (long)r * 240;         bsz = 16; }
    else if (r < 480) { bbase = Wv + (long)(r - 240) * 240; bsz = 16; }
    else              { bbase = Wk;                          bsz = 0; }

    auto seg = [&](int j) {
        return j < 16 ? 16 * h + j
             : j < 48 ? 64 + 32 * h + (j - 16)
             : j < 112 ? 192 + 64 * h + (j - 48)
             : 448 + 128 * h + (j - 112);
    };

    auto fill = [&](int s, int k0) {
        cpasync16((uint32_t)__cvta_generic_to_shared(&sA[s][ar * 20 + ac]),     abase + seg(k0 + ac),     16);
        cpasync16((uint32_t)__cvta_generic_to_shared(&sA[s][ar * 20 + ac + 4]), abase + seg(k0 + ac + 4), 16);
        cpasync16((uint32_t)__cvta_generic_to_shared(&sB[s][ar * 20 + ac]),     bbase + k0 + ac,          bsz);
        cpasync16((uint32_t)__cvta_generic_to_shared(&sB[s][ar * 20 + ac + 4]), bbase + k0 + ac + 4,      bsz);
    };

    const int KT = Dc >> 4;   // 15
    fill(0, 0);
    asm volatile("cp.async.commit_group;\n");
    for (int kt = 0; kt < KT; kt++) {
        int cur = kt & 1;
        if (kt + 1 < KT) fill(cur ^ 1, (kt + 1) << 4);
        asm volatile("cp.async.commit_group;\n");
        asm volatile("cp.async.wait_group 1;\n");
        __syncthreads();
        const float* a_s = sA[cur];
        const float* b_s = sB[cur];
        #pragma unroll
        for (int ks = 0; ks < 16; ks += 8) {
            uint32_t af[2][4], bf[8][2];
            #pragma unroll
            for (int fm = 0; fm < 2; fm++) {
                int mb = wm * 32 + fm * 16;
                af[fm][0] = f2tf(a_s[(mb + g    ) * 20 + ks + c4]);
                af[fm][1] = f2tf(a_s[(mb + g + 8) * 20 + ks + c4]);
                af[fm][2] = f2tf(a_s[(mb + g    ) * 20 + ks + c4 + 4]);
                af[fm][3] = f2tf(a_s[(mb + g + 8) * 20 + ks + c4 + 4]);
            }
            #pragma unroll
            for (int fn = 0; fn < 8; fn++) {
                int nb = wn * 64 + fn * 8 + g;
                bf[fn][0] = f2tf(b_s[nb * 20 + ks + c4]);
                bf[fn][1] = f2tf(b_s[nb * 20 + ks + c4 + 4]);
            }
            #pragma unroll
            for (int fm = 0; fm < 2; fm++)
                #pragma unroll
                for (int fn = 0; fn < 8; fn++)
                    mma_tf32(acc[fm][fn], af[fm], bf[fn]);
        }
        __syncthreads();
    }

    #pragma unroll
    for (int fm = 0; fm < 2; fm++) {
        int row0 = wm * 32 + fm * 16 + g;
        #pragma unroll
        for (int half = 0; half < 2; half++) {
            long rr = (long)(m0 + row0 + half * 8);
            #pragma unroll
            for (int fn = 0; fn < 8; fn++) {
                int col = n0 + wn * 64 + fn * 8 + c4 * 2;
                float2 v = make_float2(acc[fm][fn][half * 2], acc[fm][fn][half * 2 + 1]);
                if (col < 240)      *(float2*)(Kh + rr * 240 + col)       = v;
                else if (col < 480) *(float2*)(Vh + rr * 240 + col - 240) = v;
            }
        }
    }
}

// In-place: per (b,h) InstanceNorm over [d,240] (biased var, eps=1e-5) then softmax over k.
__global__ void norm_softmax(float* __restrict__ S, int d)
{
    float* p = S + (long)blockIdx.x * d * Dc;
    int count = d * Dc;
    float s = 0.f, ss = 0.f;
    for (int i = threadIdx.x; i < count; i += blockDim.x) {
        float v = p[i]; s += v; ss += v * v;
    }
    __shared__ float rs[8], rss[8], stats[2];
    #pragma unroll
    for (int o = 16; o; o >>= 1) {
        s  += __shfl_xor_sync(0xffffffffu, s,  o);
        ss += __shfl_xor_sync(0xffffffffu, ss, o);
    }
    int w = threadIdx.x >> 5, l = threadIdx.x & 31;
    if (l == 0) { rs[w] = s; rss[w] = ss; }
    __syncthreads();
    if (threadIdx.x == 0) {
        float a = 0.f, b2 = 0.f;
        for (int i = 0; i < 8; i++) { a += rs[i]; b2 += rss[i]; }
        float mean = a / count;
        float var  = b2 / count - mean * mean;
        stats[0] = mean;
        stats[1] = rsqrtf(var + 1e-5f);
    }
    __syncthreads();
    float mean = stats[0], istd = stats[1];

    for (int r = w; r < d; r += 8) {
        float* row = p + (long)r * Dc;
        float vals[8];
        float mx = -1e30f;
        #pragma unroll
        for (int t = 0; t < 8; t++) {
            int k = l + t * 32;
            float v = (k < Dc) ? (row[k] - mean) * istd : -1e30f;
            vals[t] = v;
            mx = fmaxf(mx, v);
        }
        #pragma unroll
        for (int o = 16; o; o >>= 1) mx = fmaxf(mx, __shfl_xor_sync(0xffffffffu, mx, o));
        float se = 0.f;
        #pragma unroll
        for (int t = 0; t < 8; t++) {
            int k = l + t * 32;
            float e = (k < Dc) ? __expf(vals[t] - mx) : 0.f;
            vals[t] = e; se += e;
        }
        #pragma unroll
        for (int o = 16; o; o >>= 1) se += __shfl_xor_sync(0xffffffffu, se, o);
        float inv = 1.f / se;
        #pragma unroll
        for (int t = 0; t < 8; t++) {
            int k = l + t * 32;
            if (k < Dc) row[k] = vals[t] * inv;
        }
    }
}

extern "C" void kernel_launch(void* const* d_in, const int* in_sizes, int n_in,
                              void* d_out, int out_size)
{
    const float* emb[4]  = { (const float*)d_in[0], (const float*)d_in[1],
                             (const float*)d_in[2], (const float*)d_in[3] };
    const float* emb_all = (const float*)d_in[4];
    const float* Wq[4]   = { (const float*)d_in[5], (const float*)d_in[6],
                             (const float*)d_in[7], (const float*)d_in[8] };
    const float* Wk      = (const float*)d_in[9];
    const float* Wv      = (const float*)d_in[10];
    const float* Wo[4]   = { (const float*)d_in[11], (const float*)d_in[12],
                             (const float*)d_in[13], (const float*)d_in[14] };
    float* out = (float*)d_out;

    float *pKh, *pVh, *pQh, *pS, *pCtxT;
    cudaGetSymbolAddress((void**)&pKh,   g_Kh);
    cudaGetSymbolAddress((void**)&pVh,   g_Vh);
    cudaGetSymbolAddress((void**)&pQh,   g_Qh);
    cudaGetSymbolAddress((void**)&pS,    g_S);
    cudaGetSymbolAddress((void**)&pCtxT, g_ctxT);

    const int dArr[4]  = {16, 32, 64, 128};
    const int chArr[4] = {64, 128, 256, 512};
    const int dcum[4]  = {0, 16, 48, 112};
    const int chcum[4] = {0, 64, 192, 448};

    // 1) fused gather + K/V projection  (M=65536, N=480, K=240)
    kvproj<<<dim3(4, 512), 256>>>(emb_all, Wk, Wv, pKh, pVh);

    const float alpha = 1.f / sqrtf((float)KVc);

    for (int sc = 0; sc < 4; sc++) {
        int d = dArr[sc], CH = chArr[sc];
        float* Qh   = pQh   + (long)Bc * Hc * Nc * dcum[sc];   // [B,H,d,N]
        float* Ss   = pS    + (long)Bc * Hc * Dc * dcum[sc];   // [B,H,d,240]
        float* ctxT = pCtxT + (long)Bc * Nc * chcum[sc];       // [B,N,CH]
        float* Osc  = out   + (long)Bc * Nc * chcum[sc];

        // 2) QhT[b,h][e,n] = sum_{d'} Wq[h][e,d'] * emb[b][n][h*d+d']   (NT per (b,h))
        {
            dim3 grid(Nc / 64, (d + 63) / 64, Bc * Hc);
            gemm64<false, false><<<grid, 128>>>(Wq[sc], emb[sc], Qh,
                d, Nc, d, d, CH, Nc, 1, Hc,
                0,                 (long)d * d,
                (long)Nc * CH,     (long)d,
                (long)Hc * Nc * d, (long)Nc * d,
                1.f);
        }
        // 3) scores[b,h][dd,k] = alpha * sum_n QhT[dd,n] * Kh[n,k]   (NN per (b,h))
        {
            dim3 grid((Dc + 63) / 64, (d + 63) / 64, Bc * Hc);
            gemm64<true, false><<<grid, 128>>>(Qh, pKh, Ss,
                d, Dc, Nc, Nc, Dc, Dc, 1, 1,
                (long)Nc * d,  0,
                (long)Nc * Dc, 0,
                (long)d * Dc,  0,
                alpha);
        }
        // 4) instance-norm + softmax (in place)
        norm_softmax<<<Bc * Hc, 256>>>(Ss, d);

        // 5) ctxT[b][n][dd*H+h] = sum_k probs[b,h][dd,k] * Vh[b,h][n,k]
        //    (NT per (b,h), strided epilogue: row dd stride H, col n stride CH, +h)
        {
            dim3 grid(Nc / 64, (d + 63) / 64, Bc * Hc);
            gemm64<false, true><<<grid, 128>>>(Ss, pVh, ctxT,
                d, Nc, Dc, Dc, Dc, Hc, CH, Hc,
                (long)Hc * d * Dc,  (long)d * Dc,
                (long)Hc * Nc * Dc, (long)Nc * Dc,
                (long)Nc * CH,      1L,
                1.f);
        }
        // 6) O = ctxT @ Wo^T   (M=16384, N=K=CH)
        if (CH >= 256) {
            dim3 grid(CH / 128, (Bc * Nc) / 128);
            gemm128<<<grid, 256>>>(ctxT, Wo[sc], Osc, Bc * Nc, CH, CH, CH, CH, CH, 1.f);
        } else {
            dim3 grid(CH / 64, (Bc * Nc) / 64, 1);
            gemm64<false, false><<<grid, 128>>>(ctxT, Wo[sc], Osc,
                Bc * Nc, CH, CH, CH, CH, CH, 1, 1,
                0, 0, 0, 0, 0, 0, 1.f);
        }
    }
}

// round 8
// speedup vs baseline: 3.8142x; 1.1020x over previous
#include <cuda_runtime.h>
#include <math.h>
#include <stdint.h>

// Problem constants
#define Bc 16
#define Nc 1024
#define Hc 4
#define KVc 960
#define Dc 240            // KV/4, per-head K/V feature dim

#define SZ_BHND (Bc*Hc*Nc*Dc)   // 15,728,640

// ---------------- scratch (static device globals; no allocation) ----------
__device__ float g_Kh  [SZ_BHND];           // [B,H,N,240]   (tf32-rounded)
__device__ float g_Vh  [SZ_BHND];           // [B,H,N,240]   (tf32-rounded)
__device__ float g_Qh  [SZ_BHND];           // per-scale [B,H,d,N]  (tf32-rounded)
__device__ float g_S   [Bc*Hc*Dc*Dc];       // per-scale [B,H,d,240]
__device__ float g_ctxT[Bc*Nc*KVc];         // per-scale [B,N,CH]   (tf32-rounded)
__device__ float g_stats[512];              // per (scale,bh): mean, istd

// ---------------- helpers ----------------
__device__ __forceinline__ void cpasync16(uint32_t dst, const void* src, int sz) {
    asm volatile("cp.async.ca.shared.global [%0], [%1], 16, %2;\n"
                 :: "r"(dst), "l"(src), "r"(sz));
}
__device__ __forceinline__ uint32_t f2tf(float f) {
    uint32_t r; asm("cvt.rna.tf32.f32 %0, %1;" : "=r"(r) : "f"(f)); return r;
}
__device__ __forceinline__ float rndtf(float f) { return __uint_as_float(f2tf(f)); }

template<bool CVT>
__device__ __forceinline__ uint32_t ldop(float v) {
    return CVT ? f2tf(v) : __float_as_uint(v);
}
__device__ __forceinline__ void mma_tf32(float* acc, const uint32_t* a, const uint32_t* b) {
    asm volatile("mma.sync.aligned.m16n8k8.row.col.f32.tf32.tf32.f32 "
                 "{%0,%1,%2,%3}, {%4,%5,%6,%7}, {%8,%9}, {%0,%1,%2,%3};\n"
                 : "+f"(acc[0]), "+f"(acc[1]), "+f"(acc[2]), "+f"(acc[3])
                 : "r"(a[0]), "r"(a[1]), "r"(a[2]), "r"(a[3]), "r"(b[0]), "r"(b[1]));
}

// =======================================================================
// 64x64 tile, 128 threads, BK=16, NT: C[m,n] = alpha * sum_k A[m,k]*B[n,k]
// SC: strided scalar C store C[r*ldc + col*ldcC]; CVTA/CVTB: in-loop tf32 cvt;
// RND: tf32-round the stored C values.
// =======================================================================
template<bool SC, bool CVTA, bool CVTB, bool RND>
__global__ __launch_bounds__(128)
void gemm64(const float* __restrict__ A, const float* __restrict__ B, float* __restrict__ C,
            int M, int Nn, int K, int lda, int ldb, int ldc, int ldcC, int Hs,
            long aB, long aH, long bB, long bH, long cB, long cH, float alpha)
{
    int z = blockIdx.z, zb = z / Hs, zh = z - zb * Hs;
    A += zb * aB + zh * aH;
    B += zb * bB + zh * bH;
    C += zb * cB + zh * cH;

    const int m0 = blockIdx.y * 64, n0 = blockIdx.x * 64;
    const int tid = threadIdx.x, lane = tid & 31, warp = tid >> 5;
    const int wm = warp >> 1, wn = warp & 1;
    const int g = lane >> 2, c4 = lane & 3;

    __shared__ float sA[2][64 * 20];
    __shared__ float sB[2][64 * 20];

    float acc[2][4][4] = {};

    const int ar = tid >> 1, ac = (tid & 1) * 8;

    auto fill = [&](int s, int k0) {
        const float* ap = A + (long)(m0 + ar) * lda + k0 + ac;
        int sa = (m0 + ar < M) ? 16 : 0;
        cpasync16((uint32_t)__cvta_generic_to_shared(&sA[s][ar * 20 + ac]),     ap,     sa);
        cpasync16((uint32_t)__cvta_generic_to_shared(&sA[s][ar * 20 + ac + 4]), ap + 4, sa);
        const float* bp = B + (long)(n0 + ar) * ldb + k0 + ac;
        int sb = (n0 + ar < Nn) ? 16 : 0;
        cpasync16((uint32_t)__cvta_generic_to_shared(&sB[s][ar * 20 + ac]),     bp,     sb);
        cpasync16((uint32_t)__cvta_generic_to_shared(&sB[s][ar * 20 + ac + 4]), bp + 4, sb);
    };

    const int KT = K >> 4;
    fill(0, 0);
    asm volatile("cp.async.commit_group;\n");
    for (int kt = 0; kt < KT; kt++) {
        int cur = kt & 1;
        if (kt + 1 < KT) fill(cur ^ 1, (kt + 1) << 4);
        asm volatile("cp.async.commit_group;\n");
        asm volatile("cp.async.wait_group 1;\n");
        __syncthreads();
        const float* a_s = sA[cur];
        const float* b_s = sB[cur];
        #pragma unroll
        for (int ks = 0; ks < 16; ks += 8) {
            uint32_t af[2][4], bf[4][2];
            #pragma unroll
            for (int fm = 0; fm < 2; fm++) {
                int mb = wm * 32 + fm * 16;
                af[fm][0] = ldop<CVTA>(a_s[(mb + g    ) * 20 + ks + c4]);
                af[fm][1] = ldop<CVTA>(a_s[(mb + g + 8) * 20 + ks + c4]);
                af[fm][2] = ldop<CVTA>(a_s[(mb + g    ) * 20 + ks + c4 + 4]);
                af[fm][3] = ldop<CVTA>(a_s[(mb + g + 8) * 20 + ks + c4 + 4]);
            }
            #pragma unroll
            for (int fn = 0; fn < 4; fn++) {
                int nb = wn * 32 + fn * 8 + g;
                bf[fn][0] = ldop<CVTB>(b_s[nb * 20 + ks + c4]);
                bf[fn][1] = ldop<CVTB>(b_s[nb * 20 + ks + c4 + 4]);
            }
            #pragma unroll
            for (int fm = 0; fm < 2; fm++)
                #pragma unroll
                for (int fn = 0; fn < 4; fn++)
                    mma_tf32(acc[fm][fn], af[fm], bf[fn]);
        }
        __syncthreads();
    }

    #pragma unroll
    for (int fm = 0; fm < 2; fm++) {
        int row0 = m0 + wm * 32 + fm * 16 + g;
        #pragma unroll
        for (int half = 0; half < 2; half++) {
            int r = row0 + half * 8;
            if (r >= M) continue;
            #pragma unroll
            for (int fn = 0; fn < 4; fn++) {
                int col = n0 + wn * 32 + fn * 8 + c4 * 2;
                if (col >= Nn) continue;
                float v0 = alpha * acc[fm][fn][half * 2 + 0];
                float v1 = alpha * acc[fm][fn][half * 2 + 1];
                if (RND) { v0 = rndtf(v0); v1 = rndtf(v1); }
                if (SC) {
                    C[(long)r * ldc + (long)col * ldcC] = v0;
                    C[(long)r * ldc + (long)(col + 1) * ldcC] = v1;
                } else {
                    *(float2*)(C + (long)r * ldc + col) = make_float2(v0, v1);
                }
            }
        }
    }
}

// =======================================================================
// 128x128 tile, 256 threads, BK=16 — NT: C = alpha*A*B^T
// =======================================================================
template<bool CVTA, bool CVTB>
__global__ __launch_bounds__(256)
void gemm128(const float* __restrict__ A, const float* __restrict__ B, float* __restrict__ C,
             int M, int Nn, int K, int lda, int ldb, int ldc, float alpha)
{
    const int m0 = blockIdx.y * 128, n0 = blockIdx.x * 128;
    const int tid = threadIdx.x, lane = tid & 31, warp = tid >> 5;
    const int wm = warp >> 1, wn = warp & 1;   // 4x2 warps: warp tile 32x64
    const int g = lane >> 2, c4 = lane & 3;

    __shared__ float sA[2][128 * 20];
    __shared__ float sB[2][128 * 20];

    float acc[2][8][4] = {};

    const int ar = tid >> 1, ac = (tid & 1) * 8;

    auto fill = [&](int s, int k0) {
        const float* ap = A + (long)(m0 + ar) * lda + k0 + ac;
        int sa = (m0 + ar < M) ? 16 : 0;
        cpasync16((uint32_t)__cvta_generic_to_shared(&sA[s][ar * 20 + ac]),     ap,     sa);
        cpasync16((uint32_t)__cvta_generic_to_shared(&sA[s][ar * 20 + ac + 4]), ap + 4, sa);
        const float* bp = B + (long)(n0 + ar) * ldb + k0 + ac;
        int sb = (n0 + ar < Nn) ? 16 : 0;
        cpasync16((uint32_t)__cvta_generic_to_shared(&sB[s][ar * 20 + ac]),     bp,     sb);
        cpasync16((uint32_t)__cvta_generic_to_shared(&sB[s][ar * 20 + ac + 4]), bp + 4, sb);
    };

    const int KT = K >> 4;
    fill(0, 0);
    asm volatile("cp.async.commit_group;\n");
    for (int kt = 0; kt < KT; kt++) {
        int cur = kt & 1;
        if (kt + 1 < KT) fill(cur ^ 1, (kt + 1) << 4);
        asm volatile("cp.async.commit_group;\n");
        asm volatile("cp.async.wait_group 1;\n");
        __syncthreads();
        const float* a_s = sA[cur];
        const float* b_s = sB[cur];
        #pragma unroll
        for (int ks = 0; ks < 16; ks += 8) {
            uint32_t af[2][4], bf[8][2];
            #pragma unroll
            for (int fm = 0; fm < 2; fm++) {
                int mb = wm * 32 + fm * 16;
                af[fm][0] = ldop<CVTA>(a_s[(mb + g    ) * 20 + ks + c4]);
                af[fm][1] = ldop<CVTA>(a_s[(mb + g + 8) * 20 + ks + c4]);
                af[fm][2] = ldop<CVTA>(a_s[(mb + g    ) * 20 + ks + c4 + 4]);
                af[fm][3] = ldop<CVTA>(a_s[(mb + g + 8) * 20 + ks + c4 + 4]);
            }
            #pragma unroll
            for (int fn = 0; fn < 8; fn++) {
                int nb = wn * 64 + fn * 8 + g;
                bf[fn][0] = ldop<CVTB>(b_s[nb * 20 + ks + c4]);
                bf[fn][1] = ldop<CVTB>(b_s[nb * 20 + ks + c4 + 4]);
            }
            #pragma unroll
            for (int fm = 0; fm < 2; fm++)
                #pragma unroll
                for (int fn = 0; fn < 8; fn++)
                    mma_tf32(acc[fm][fn], af[fm], bf[fn]);
        }
        __syncthreads();
    }

    #pragma unroll
    for (int fm = 0; fm < 2; fm++) {
        int row0 = m0 + wm * 32 + fm * 16 + g;
        #pragma unroll
        for (int half = 0; half < 2; half++) {
            int r = row0 + half * 8;
            if (r >= M) continue;
            #pragma unroll
            for (int fn = 0; fn < 8; fn++) {
                int col = n0 + wn * 64 + fn * 8 + c4 * 2;
                if (col >= Nn) continue;
                *(float2*)(C + (long)r * ldc + col) =
                    make_float2(alpha * acc[fm][fn][half * 2], alpha * acc[fm][fn][half * 2 + 1]);
            }
        }
    }
}

// =======================================================================
// Fused gather + K/V projection (128x128 tile). Outputs tf32-rounded.
// =======================================================================
__global__ __launch_bounds__(256)
void kvproj(const float* __restrict__ emb_all, const float* __restrict__ Wk,
            const float* __restrict__ Wv, float* __restrict__ Kh, float* __restrict__ Vh)
{
    const int m0 = blockIdx.y * 128, n0 = blockIdx.x * 128;
    const int tid = threadIdx.x, lane = tid & 31, warp = tid >> 5;
    const int wm = warp >> 1, wn = warp & 1;
    const int g = lane >> 2, c4 = lane & 3;

    __shared__ float sA[2][128 * 20];
    __shared__ float sB[2][128 * 20];

    float acc[2][8][4] = {};

    const int ar = tid >> 1, ac = (tid & 1) * 8;

    int m = m0 + ar;
    int b = m >> 12, h = (m >> 10) & 3, n = m & 1023;
    const float* abase = emb_all + ((long)(b * Nc + n)) * KVc;

    int r = n0 + ar;
    const float* bbase;
    int bsz;
    if (r < 240)      { bbase = Wk + (long)r * 240;         bsz = 16; }
    else if (r < 480) { bbase = Wv + (long)(r - 240) * 240; bsz = 16; }
    else              { bbase = Wk;                          bsz = 0; }

    auto seg = [&](int j) {
        return j < 16 ? 16 * h + j
             : j < 48 ? 64 + 32 * h + (j - 16)
             : j < 112 ? 192 + 64 * h + (j - 48)
             : 448 + 128 * h + (j - 112);
    };

    auto fill = [&](int s, int k0) {
        cpasync16((uint32_t)__cvta_generic_to_shared(&sA[s][ar * 20 + ac]),     abase + seg(k0 + ac),     16);
        cpasync16((uint32_t)__cvta_generic_to_shared(&sA[s][ar * 20 + ac + 4]), abase + seg(k0 + ac + 4), 16);
        cpasync16((uint32_t)__cvta_generic_to_shared(&sB[s][ar * 20 + ac]),     bbase + k0 + ac,          bsz);
        cpasync16((uint32_t)__cvta_generic_to_shared(&sB[s][ar * 20 + ac + 4]), bbase + k0 + ac + 4,      bsz);
    };

    const int KT = Dc >> 4;   // 15
    fill(0, 0);
    asm volatile("cp.async.commit_group;\n");
    for (int kt = 0; kt < KT; kt++) {
        int cur = kt & 1;
        if (kt + 1 < KT) fill(cur ^ 1, (kt + 1) << 4);
        asm volatile("cp.async.commit_group;\n");
        asm volatile("cp.async.wait_group 1;\n");
        __syncthreads();
        const float* a_s = sA[cur];
        const float* b_s = sB[cur];
        #pragma unroll
        for (int ks = 0; ks < 16; ks += 8) {
            uint32_t af[2][4], bf[8][2];
            #pragma unroll
            for (int fm = 0; fm < 2; fm++) {
                int mb = wm * 32 + fm * 16;
                af[fm][0] = f2tf(a_s[(mb + g    ) * 20 + ks + c4]);
                af[fm][1] = f2tf(a_s[(mb + g + 8) * 20 + ks + c4]);
                af[fm][2] = f2tf(a_s[(mb + g    ) * 20 + ks + c4 + 4]);
                af[fm][3] = f2tf(a_s[(mb + g + 8) * 20 + ks + c4 + 4]);
            }
            #pragma unroll
            for (int fn = 0; fn < 8; fn++) {
                int nb = wn * 64 + fn * 8 + g;
                bf[fn][0] = f2tf(b_s[nb * 20 + ks + c4]);
                bf[fn][1] = f2tf(b_s[nb * 20 + ks + c4 + 4]);
            }
            #pragma unroll
            for (int fm = 0; fm < 2; fm++)
                #pragma unroll
                for (int fn = 0; fn < 8; fn++)
                    mma_tf32(acc[fm][fn], af[fm], bf[fn]);
        }
        __syncthreads();
    }

    #pragma unroll
    for (int fm = 0; fm < 2; fm++) {
        int row0 = wm * 32 + fm * 16 + g;
        #pragma unroll
        for (int half = 0; half < 2; half++) {
            long rr = (long)(m0 + row0 + half * 8);
            #pragma unroll
            for (int fn = 0; fn < 8; fn++) {
                int col = n0 + wn * 64 + fn * 8 + c4 * 2;
                float2 v = make_float2(rndtf(acc[fm][fn][half * 2]),
                                       rndtf(acc[fm][fn][half * 2 + 1]));
                if (col < 240)      *(float2*)(Kh + rr * 240 + col)       = v;
                else if (col < 480) *(float2*)(Vh + rr * 240 + col - 240) = v;
            }
        }
    }
}

// =======================================================================
// All-scale score GEMM: one launch, z = (scale<<6)|bh.
// C[dd,k] = alpha * sum_n Qh[dd,n] * Kh[n,k]; block tile 64 x 240.
// Operands are pre-rounded tf32 -> no in-loop cvt.
// =======================================================================
__global__ __launch_bounds__(256)
void score_all(const float* __restrict__ Qh, const float* __restrict__ Kh,
               float* __restrict__ S, float alpha)
{
    const int z = blockIdx.z, sc = z >> 6, bh = z & 63;
    const int d = 16 << sc, dc = d - 16;    // dcum = 16*(2^sc - 1)
    const int m0 = blockIdx.y * 64;
    if (m0 >= d) return;

    const float* A = Qh + 65536L * dc + (long)bh * d * 1024;   // [d,1024]
    const float* B = Kh + (long)bh * 1024 * 240;               // [1024,240]
    float*       C = S  + 15360L * dc + (long)bh * d * 240;    // [d,240]

    const int tid = threadIdx.x, lane = tid & 31, warp = tid >> 5;
    const int wm = warp >> 2, wn = warp & 3;      // 2 x 4 warps, warp tile 32 x 64
    const int g = lane >> 2, c4 = lane & 3;

    __shared__ float sA[2][64 * 20];
    __shared__ float sB[2][16 * 264];

    float acc[2][8][4] = {};

    const int ar = tid >> 2, ac = (tid & 3) * 4;    // A: 64x16, 1 float4/thread
    const int br = tid >> 4, bc0 = (tid & 15) * 16; // B: 16x256, 4 float4/thread

    auto fill = [&](int s, int k0) {
        cpasync16((uint32_t)__cvta_generic_to_shared(&sA[s][ar * 20 + ac]),
                  A + (long)(m0 + ar) * 1024 + k0 + ac, (m0 + ar < d) ? 16 : 0);
        #pragma unroll
        for (int j = 0; j < 4; j++) {
            int col = bc0 + j * 4;
            cpasync16((uint32_t)__cvta_generic_to_shared(&sB[s][br * 264 + col]),
                      B + (long)(k0 + br) * 240 + col, (col < 240) ? 16 : 0);
        }
    };

    const int KT = 64;   // K = 1024, BK = 16
    fill(0, 0);
    asm volatile("cp.async.commit_group;\n");
    for (int kt = 0; kt < KT; kt++) {
        int cur = kt & 1;
        if (kt + 1 < KT) fill(cur ^ 1, (kt + 1) << 4);
        asm volatile("cp.async.commit_group;\n");
        asm volatile("cp.async.wait_group 1;\n");
        __syncthreads();
        const float* a_s = sA[cur];
        const float* b_s = sB[cur];
        #pragma unroll
        for (int ks = 0; ks < 16; ks += 8) {
            uint32_t af[2][4], bf[8][2];
            #pragma unroll
            for (int fm = 0; fm < 2; fm++) {
                int mb = wm * 32 + fm * 16;
                af[fm][0] = __float_as_uint(a_s[(mb + g    ) * 20 + ks + c4]);
                af[fm][1] = __float_as_uint(a_s[(mb + g + 8) * 20 + ks + c4]);
                af[fm][2] = __float_as_uint(a_s[(mb + g    ) * 20 + ks + c4 + 4]);
                af[fm][3] = __float_as_uint(a_s[(mb + g + 8) * 20 + ks + c4 + 4]);
            }
            #pragma unroll
            for (int fn = 0; fn < 8; fn++) {
                int nb = wn * 64 + fn * 8 + g;
                bf[fn][0] = __float_as_uint(b_s[(ks + c4    ) * 264 + nb]);
                bf[fn][1] = __float_as_uint(b_s[(ks + c4 + 4) * 264 + nb]);
            }
            #pragma unroll
            for (int fm = 0; fm < 2; fm++)
                #pragma unroll
                for (int fn = 0; fn < 8; fn++)
                    mma_tf32(acc[fm][fn], af[fm], bf[fn]);
        }
        __syncthreads();
    }

    #pragma unroll
    for (int fm = 0; fm < 2; fm++) {
        int row0 = m0 + wm * 32 + fm * 16 + g;
        #pragma unroll
        for (int half = 0; half < 2; half++) {
            int r = row0 + half * 8;
            if (r >= d) continue;
            #pragma unroll
            for (int fn = 0; fn < 8; fn++) {
                int col = wn * 64 + fn * 8 + c4 * 2;
                if (col >= 240) continue;
                *(float2*)(C + (long)r * 240 + col) =
                    make_float2(alpha * acc[fm][fn][half * 2],
                                alpha * acc[fm][fn][half * 2 + 1]);
            }
        }
    }
}

// =======================================================================
// InstanceNorm stats: one block per (scale,bh); biased var, eps=1e-5.
// =======================================================================
__global__ void stats_all(const float* __restrict__ S, float* __restrict__ stats)
{
    const int i = blockIdx.x, sc = i >> 6, bh = i & 63;
    const int d = 16 << sc, dc = d - 16;
    const float* p = S + 15360L * dc + (long)bh * d * 240;
    const int count = d * 240;

    float s = 0.f, ss = 0.f;
    for (int j = threadIdx.x; j < count; j += blockDim.x) {
        float v = p[j]; s += v; ss += v * v;
    }
    __shared__ float rs[8], rss[8];
    #pragma unroll
    for (int o = 16; o; o >>= 1) {
        s  += __shfl_xor_sync(0xffffffffu, s,  o);
        ss += __shfl_xor_sync(0xffffffffu, ss, o);
    }
    int w = threadIdx.x >> 5, l = threadIdx.x & 31;
    if (l == 0) { rs[w] = s; rss[w] = ss; }
    __syncthreads();
    if (threadIdx.x == 0) {
        float a = 0.f, b2 = 0.f;
        for (int j = 0; j < 8; j++) { a += rs[j]; b2 += rss[j]; }
        float mean = a / count;
        float var  = b2 / count - mean * mean;
        stats[2 * i]     = mean;
        stats[2 * i + 1] = rsqrtf(var + 1e-5f);
    }
}

// =======================================================================
// Softmax apply: one warp per score row (240 elems); writes tf32-rounded probs.
// Global rows: sc0 [0,1024), sc1 [1024,3072), sc2 [3072,7168), sc3 [7168,15360).
// =======================================================================
__global__ __launch_bounds__(256)
void softmax_all(float* __restrict__ S, const float* __restrict__ stats)
{
    int row = blockIdx.x * 8 + (threadIdx.x >> 5);
    int l = threadIdx.x & 31;
    int sc, loc;
    if (row < 1024)      { sc = 0; loc = row; }
    else if (row < 3072) { sc = 1; loc = row - 1024; }
    else if (row < 7168) { sc = 2; loc = row - 3072; }
    else                 { sc = 3; loc = row - 7168; }
    int d = 16 << sc, dc = d - 16;
    int bh = loc >> (4 + sc);
    float* p = S + 15360L * dc + (long)loc * 240;
    float mean = stats[2 * ((sc << 6) | bh)];
    float istd = stats[2 * ((sc << 6) | bh) + 1];

    float v[8];
    float mx = -1e30f;
    #pragma unroll
    for (int t = 0; t < 8; t++) {
        int k = l + t * 32;
        float x = (k < 240) ? (p[k] - mean) * istd : -1e30f;
        v[t] = x; mx = fmaxf(mx, x);
    }
    #pragma unroll
    for (int o = 16; o; o >>= 1) mx = fmaxf(mx, __shfl_xor_sync(0xffffffffu, mx, o));
    float se = 0.f;
    #pragma unroll
    for (int t = 0; t < 8; t++) {
        int k = l + t * 32;
        float e = (k < 240) ? __expf(v[t] - mx) : 0.f;
        v[t] = e; se += e;
    }
    #pragma unroll
    for (int o = 16; o; o >>= 1) se += __shfl_xor_sync(0xffffffffu, se, o);
    float inv = 1.f / se;
    #pragma unroll
    for (int t = 0; t < 8; t++) {
        int k = l + t * 32;
        if (k < 240) p[k] = rndtf(v[t] * inv);
    }
}

extern "C" void kernel_launch(void* const* d_in, const int* in_sizes, int n_in,
                              void* d_out, int out_size)
{
    const float* emb[4]  = { (const float*)d_in[0], (const float*)d_in[1],
                             (const float*)d_in[2], (const float*)d_in[3] };
    const float* emb_all = (const float*)d_in[4];
    const float* Wq[4]   = { (const float*)d_in[5], (const float*)d_in[6],
                             (const float*)d_in[7], (const float*)d_in[8] };
    const float* Wk      = (const float*)d_in[9];
    const float* Wv      = (const float*)d_in[10];
    const float* Wo[4]   = { (const float*)d_in[11], (const float*)d_in[12],
                             (const float*)d_in[13], (const float*)d_in[14] };
    float* out = (float*)d_out;

    float *pKh, *pVh, *pQh, *pS, *pCtxT, *pStats;
    cudaGetSymbolAddress((void**)&pKh,    g_Kh);
    cudaGetSymbolAddress((void**)&pVh,    g_Vh);
    cudaGetSymbolAddress((void**)&pQh,    g_Qh);
    cudaGetSymbolAddress((void**)&pS,     g_S);
    cudaGetSymbolAddress((void**)&pCtxT,  g_ctxT);
    cudaGetSymbolAddress((void**)&pStats, g_stats);

    const int dArr[4]  = {16, 32, 64, 128};
    const int chArr[4] = {64, 128, 256, 512};
    const int dcum[4]  = {0, 16, 48, 112};
    const int chcum[4] = {0, 64, 192, 448};

    // 1) fused gather + K/V projection  (M=65536, N=480, K=240) — rounded outputs
    kvproj<<<dim3(4, 512), 256>>>(emb_all, Wk, Wv, pKh, pVh);

    // 2) Q projections (rounded outputs)
    for (int sc = 0; sc < 4; sc++) {
        int d = dArr[sc], CH = chArr[sc];
        float* Qh = pQh + (long)Bc * Hc * Nc * dcum[sc];
        dim3 grid(Nc / 64, (d + 63) / 64, Bc * Hc);
        gemm64<false, true, true, true><<<grid, 128>>>(Wq[sc], emb[sc], Qh,
            d, Nc, d, d, CH, Nc, 1, Hc,
            0,                 (long)d * d,
            (long)Nc * CH,     (long)d,
            (long)Hc * Nc * d, (long)Nc * d,
            1.f);
    }

    const float alpha = 1.f / sqrtf((float)KVc);

    // 3) all score GEMMs in one launch (no in-loop cvt; Qh read once)
    score_all<<<dim3(1, 2, 256), 256>>>(pQh, pKh, pS, alpha);

    // 4) instance-norm stats + softmax apply (rounded probs)
    stats_all<<<256, 256>>>(pS, pStats);
    softmax_all<<<15360 / 8, 256>>>(pS, pStats);

    // 5) ctx + output projection per scale
    for (int sc = 0; sc < 4; sc++) {
        int d = dArr[sc], CH = chArr[sc];
        float* Ss   = pS    + (long)Bc * Hc * Dc * dcum[sc];
        float* ctxT = pCtxT + (long)Bc * Nc * chcum[sc];
        float* Osc  = out   + (long)Bc * Nc * chcum[sc];

        // ctxT[b][n][dd*H+h] = sum_k probs[dd,k] * Vh[n,k]  (no cvt; rounded store)
        {
            dim3 grid(Nc / 64, (d + 63) / 64, Bc * Hc);
            gemm64<true, false, false, true><<<grid, 128>>>(Ss, pVh, ctxT,
                d, Nc, Dc, Dc, Dc, Hc, CH, Hc,
                (long)Hc * d * Dc,  (long)d * Dc,
                (long)Hc * Nc * Dc, (long)Nc * Dc,
                (long)Nc * CH,      1L,
                1.f);
        }
        // O = ctxT @ Wo^T  (A pre-rounded; cvt only B; full-precision store)
        if (CH >= 256) {
            dim3 grid(CH / 128, (Bc * Nc) / 128);
            gemm128<false, true><<<grid, 256>>>(ctxT, Wo[sc], Osc,
                                                Bc * Nc, CH, CH, CH, CH, CH, 1.f);
        } else {
            dim3 grid(CH / 64, (Bc * Nc) / 64, 1);
            gemm64<false, false, true, false><<<grid, 128>>>(ctxT, Wo[sc], Osc,
                Bc * Nc, CH, CH, CH, CH, CH, 1, 1,
                0, 0, 0, 0, 0, 0, 1.f);
        }
    }
}

// round 9
// speedup vs baseline: 4.1376x; 1.0848x over previous
#include <cuda_runtime.h>
#include <math.h>
#include <stdint.h>

// Problem constants
#define Bc 16
#define Nc 1024
#define Hc 4
#define KVc 960
#define Dc 240            // KV/4, per-head K/V feature dim

#define SZ_BHND (Bc*Hc*Nc*Dc)   // 15,728,640

// ---------------- scratch (static device globals; no allocation) ----------
__device__ float g_KhT [SZ_BHND];           // [bh][240][1024]  (tf32-rounded, TRANSPOSED)
__device__ float g_Vh  [SZ_BHND];           // [bh][1024][240]  (tf32-rounded)
__device__ float g_Qh  [SZ_BHND];           // per-scale [bh][d][1024] (tf32-rounded)
__device__ float g_S   [Bc*Hc*Dc*Dc];       // per-scale [bh][d][240]
__device__ float g_ctxT[Bc*Nc*KVc];         // per-scale [B,N,CH] (tf32-rounded)
__device__ float g_stats[512];              // per (scale,bh): mean, istd

// ---------------- helpers ----------------
__device__ __forceinline__ void cpasync16(uint32_t dst, const void* src, int sz) {
    asm volatile("cp.async.ca.shared.global [%0], [%1], 16, %2;\n"
                 :: "r"(dst), "l"(src), "r"(sz));
}
__device__ __forceinline__ uint32_t f2tf(float f) {
    uint32_t r; asm("cvt.rna.tf32.f32 %0, %1;" : "=r"(r) : "f"(f)); return r;
}
__device__ __forceinline__ float rndtf(float f) { return __uint_as_float(f2tf(f)); }

template<bool CVT>
__device__ __forceinline__ uint32_t ldop(float v) {
    return CVT ? f2tf(v) : __float_as_uint(v);
}
__device__ __forceinline__ void mma_tf32(float* acc, const uint32_t* a, const uint32_t* b) {
    asm volatile("mma.sync.aligned.m16n8k8.row.col.f32.tf32.tf32.f32 "
                 "{%0,%1,%2,%3}, {%4,%5,%6,%7}, {%8,%9}, {%0,%1,%2,%3};\n"
                 : "+f"(acc[0]), "+f"(acc[1]), "+f"(acc[2]), "+f"(acc[3])
                 : "r"(a[0]), "r"(a[1]), "r"(a[2]), "r"(a[3]), "r"(b[0]), "r"(b[1]));
}
__device__ __forceinline__ void ldsm4(uint32_t* r, uint32_t addr) {
    asm volatile("ldmatrix.sync.aligned.m8n8.x4.shared.b16 {%0,%1,%2,%3}, [%4];\n"
                 : "=r"(r[0]), "=r"(r[1]), "=r"(r[2]), "=r"(r[3]) : "r"(addr));
}

// =======================================================================
// Shared 64x64 GEMM body: 128 threads, BK=16, NT (B [Nn][K] K-contig).
// =======================================================================
template<bool SC, bool CVTA, bool CVTB, bool RND>
__device__ __forceinline__
void gemm64_body(const float* __restrict__ A, const float* __restrict__ B, float* __restrict__ C,
                 int M, int Nn, int K, int lda, int ldb, int ldc, int ldcC,
                 int m0, int n0, float alpha)
{
    const int tid = threadIdx.x, lane = tid & 31, warp = tid >> 5;
    const int wm = warp >> 1, wn = warp & 1;
    const int g = lane >> 2, c4 = lane & 3;

    __shared__ float sA[2][64 * 20];
    __shared__ float sB[2][64 * 20];

    float acc[2][4][4] = {};

    const int ar = tid >> 1, ac = (tid & 1) * 8;

    auto fill = [&](int s, int k0) {
        const float* ap = A + (long)(m0 + ar) * lda + k0 + ac;
        int sa = (m0 + ar < M) ? 16 : 0;
        cpasync16((uint32_t)__cvta_generic_to_shared(&sA[s][ar * 20 + ac]),     ap,     sa);
        cpasync16((uint32_t)__cvta_generic_to_shared(&sA[s][ar * 20 + ac + 4]), ap + 4, sa);
        const float* bp = B + (long)(n0 + ar) * ldb + k0 + ac;
        int sb = (n0 + ar < Nn) ? 16 : 0;
        cpasync16((uint32_t)__cvta_generic_to_shared(&sB[s][ar * 20 + ac]),     bp,     sb);
        cpasync16((uint32_t)__cvta_generic_to_shared(&sB[s][ar * 20 + ac + 4]), bp + 4, sb);
    };

    const int KT = K >> 4;
    fill(0, 0);
    asm volatile("cp.async.commit_group;\n");
    for (int kt = 0; kt < KT; kt++) {
        int cur = kt & 1;
        if (kt + 1 < KT) fill(cur ^ 1, (kt + 1) << 4);
        asm volatile("cp.async.commit_group;\n");
        asm volatile("cp.async.wait_group 1;\n");
        __syncthreads();
        const float* a_s = sA[cur];
        const float* b_s = sB[cur];
        #pragma unroll
        for (int ks = 0; ks < 16; ks += 8) {
            uint32_t af[2][4], bf[4][2];
            #pragma unroll
            for (int fm = 0; fm < 2; fm++) {
                int mb = wm * 32 + fm * 16;
                af[fm][0] = ldop<CVTA>(a_s[(mb + g    ) * 20 + ks + c4]);
                af[fm][1] = ldop<CVTA>(a_s[(mb + g + 8) * 20 + ks + c4]);
                af[fm][2] = ldop<CVTA>(a_s[(mb + g    ) * 20 + ks + c4 + 4]);
                af[fm][3] = ldop<CVTA>(a_s[(mb + g + 8) * 20 + ks + c4 + 4]);
            }
            #pragma unroll
            for (int fn = 0; fn < 4; fn++) {
                int nb = wn * 32 + fn * 8 + g;
                bf[fn][0] = ldop<CVTB>(b_s[nb * 20 + ks + c4]);
                bf[fn][1] = ldop<CVTB>(b_s[nb * 20 + ks + c4 + 4]);
            }
            #pragma unroll
            for (int fm = 0; fm < 2; fm++)
                #pragma unroll
                for (int fn = 0; fn < 4; fn++)
                    mma_tf32(acc[fm][fn], af[fm], bf[fn]);
        }
        __syncthreads();
    }

    #pragma unroll
    for (int fm = 0; fm < 2; fm++) {
        int row0 = m0 + wm * 32 + fm * 16 + g;
        #pragma unroll
        for (int half = 0; half < 2; half++) {
            int r = row0 + half * 8;
            if (r >= M) continue;
            #pragma unroll
            for (int fn = 0; fn < 4; fn++) {
                int col = n0 + wn * 32 + fn * 8 + c4 * 2;
                if (col >= Nn) continue;
                float v0 = alpha * acc[fm][fn][half * 2 + 0];
                float v1 = alpha * acc[fm][fn][half * 2 + 1];
                if (RND) { v0 = rndtf(v0); v1 = rndtf(v1); }
                if (SC) {
                    C[(long)r * ldc + (long)col * ldcC] = v0;
                    C[(long)r * ldc + (long)(col + 1) * ldcC] = v1;
                } else {
                    *(float2*)(C + (long)r * ldc + col) = make_float2(v0, v1);
                }
            }
        }
    }
}

// Generic 64x64 kernel (used for out-proj CH=64/128)
template<bool SC, bool CVTA, bool CVTB, bool RND>
__global__ __launch_bounds__(128)
void gemm64(const float* __restrict__ A, const float* __restrict__ B, float* __restrict__ C,
            int M, int Nn, int K, int lda, int ldb, int ldc, int ldcC, int Hs,
            long aB, long aH, long bB, long bH, long cB, long cH, float alpha)
{
    int z = blockIdx.z, zb = z / Hs, zh = z - zb * Hs;
    gemm64_body<SC, CVTA, CVTB, RND>(A + zb * aB + zh * aH, B + zb * bB + zh * bH,
                                     C + zb * cB + zh * cH,
                                     M, Nn, K, lda, ldb, ldc, ldcC,
                                     blockIdx.y * 64, blockIdx.x * 64, alpha);
}

// All-scale Q projection: z = (sc<<6)|bh. QhT[sc][bh][e][n], rounded.
__global__ __launch_bounds__(128)
void qproj_all(const float* __restrict__ e1, const float* __restrict__ e2,
               const float* __restrict__ e3, const float* __restrict__ e4,
               const float* __restrict__ w1, const float* __restrict__ w2,
               const float* __restrict__ w3, const float* __restrict__ w4,
               float* __restrict__ Qh)
{
    const int z = blockIdx.z, sc = z >> 6, bh = z & 63, b = bh >> 2, h = bh & 3;
    const int d = 16 << sc, CH = d * 4;
    const int m0 = blockIdx.y * 64;
    if (m0 >= d) return;
    const float* emb = sc == 0 ? e1 : sc == 1 ? e2 : sc == 2 ? e3 : e4;
    const float* Wq  = sc == 0 ? w1 : sc == 1 ? w2 : sc == 2 ? w3 : w4;
    const float* A = Wq + (long)h * d * d;                 // [d][d]
    const float* B = emb + (long)b * 1024 * CH + h * d;    // [1024][CH]
    float*       C = Qh + 65536L * (d - 16) + (long)bh * d * 1024;  // [d][1024]
    gemm64_body<false, true, true, true>(A, B, C, d, 1024, d, d, CH, 1024, 1,
                                         m0, blockIdx.x * 64, 1.f);
}

// All-scale ctx GEMM: z = (sc<<6)|bh. ctxT[b][n][dd*H+h], rounded.
__global__ __launch_bounds__(128)
void ctx_all(const float* __restrict__ S, const float* __restrict__ Vh,
             float* __restrict__ ctxT)
{
    const int z = blockIdx.z, sc = z >> 6, bh = z & 63, b = bh >> 2, h = bh & 3;
    const int d = 16 << sc, CH = d * 4;
    const int m0 = blockIdx.y * 64;
    if (m0 >= d) return;
    const float* A = S  + 15360L * (d - 16) + (long)bh * d * 240;   // [d][240]
    const float* B = Vh + (long)bh * 1024 * 240;                    // [1024][240]
    float*       C = ctxT + 65536L * (d - 16) + (long)b * 1024 * CH + h;
    gemm64_body<true, false, false, true>(A, B, C, d, 1024, 240, 240, 240, Hc, CH,
                                          m0, blockIdx.x * 64, 1.f);
}

// =======================================================================
// 128x128 tile, 256 threads, BK=16 — NT: C = alpha*A*B^T
// =======================================================================
template<bool CVTA, bool CVTB>
__global__ __launch_bounds__(256)
void gemm128(const float* __restrict__ A, const float* __restrict__ B, float* __restrict__ C,
             int M, int Nn, int K, int lda, int ldb, int ldc, float alpha)
{
    const int m0 = blockIdx.y * 128, n0 = blockIdx.x * 128;
    const int tid = threadIdx.x, lane = tid & 31, warp = tid >> 5;
    const int wm = warp >> 1, wn = warp & 1;   // 4x2 warps: warp tile 32x64
    const int g = lane >> 2, c4 = lane & 3;

    __shared__ float sA[2][128 * 20];
    __shared__ float sB[2][128 * 20];

    float acc[2][8][4] = {};

    const int ar = tid >> 1, ac = (tid & 1) * 8;

    auto fill = [&](int s, int k0) {
        const float* ap = A + (long)(m0 + ar) * lda + k0 + ac;
        int sa = (m0 + ar < M) ? 16 : 0;
        cpasync16((uint32_t)__cvta_generic_to_shared(&sA[s][ar * 20 + ac]),     ap,     sa);
        cpasync16((uint32_t)__cvta_generic_to_shared(&sA[s][ar * 20 + ac + 4]), ap + 4, sa);
        const float* bp = B + (long)(n0 + ar) * ldb + k0 + ac;
        int sb = (n0 + ar < Nn) ? 16 : 0;
        cpasync16((uint32_t)__cvta_generic_to_shared(&sB[s][ar * 20 + ac]),     bp,     sb);
        cpasync16((uint32_t)__cvta_generic_to_shared(&sB[s][ar * 20 + ac + 4]), bp + 4, sb);
    };

    const int KT = K >> 4;
    fill(0, 0);
    asm volatile("cp.async.commit_group;\n");
    for (int kt = 0; kt < KT; kt++) {
        int cur = kt & 1;
        if (kt + 1 < KT) fill(cur ^ 1, (kt + 1) << 4);
        asm volatile("cp.async.commit_group;\n");
        asm volatile("cp.async.wait_group 1;\n");
        __syncthreads();
        const float* a_s = sA[cur];
        const float* b_s = sB[cur];
        #pragma unroll
        for (int ks = 0; ks < 16; ks += 8) {
            uint32_t af[2][4], bf[8][2];
            #pragma unroll
            for (int fm = 0; fm < 2; fm++) {
                int mb = wm * 32 + fm * 16;
                af[fm][0] = ldop<CVTA>(a_s[(mb + g    ) * 20 + ks + c4]);
                af[fm][1] = ldop<CVTA>(a_s[(mb + g + 8) * 20 + ks + c4]);
                af[fm][2] = ldop<CVTA>(a_s[(mb + g    ) * 20 + ks + c4 + 4]);
                af[fm][3] = ldop<CVTA>(a_s[(mb + g + 8) * 20 + ks + c4 + 4]);
            }
            #pragma unroll
            for (int fn = 0; fn < 8; fn++) {
                int nb = wn * 64 + fn * 8 + g;
                bf[fn][0] = ldop<CVTB>(b_s[nb * 20 + ks + c4]);
                bf[fn][1] = ldop<CVTB>(b_s[nb * 20 + ks + c4 + 4]);
            }
            #pragma unroll
            for (int fm = 0; fm < 2; fm++)
                #pragma unroll
                for (int fn = 0; fn < 8; fn++)
                    mma_tf32(acc[fm][fn], af[fm], bf[fn]);
        }
        __syncthreads();
    }

    #pragma unroll
    for (int fm = 0; fm < 2; fm++) {
        int row0 = m0 + wm * 32 + fm * 16 + g;
        #pragma unroll
        for (int half = 0; half < 2; half++) {
            int r = row0 + half * 8;
            if (r >= M) continue;
            #pragma unroll
            for (int fn = 0; fn < 8; fn++) {
                int col = n0 + wn * 64 + fn * 8 + c4 * 2;
                if (col >= Nn) continue;
                *(float2*)(C + (long)r * ldc + col) =
                    make_float2(alpha * acc[fm][fn][half * 2], alpha * acc[fm][fn][half * 2 + 1]);
            }
        }
    }
}

// =======================================================================
// Fused gather + K/V projection (128x128 tile). Rounded outputs.
// Kh written TRANSPOSED: KhT[bh][c][n]; Vh written [bh][n][c].
// =======================================================================
__global__ __launch_bounds__(256)
void kvproj(const float* __restrict__ emb_all, const float* __restrict__ Wk,
            const float* __restrict__ Wv, float* __restrict__ KhT, float* __restrict__ Vh)
{
    const int m0 = blockIdx.y * 128, n0 = blockIdx.x * 128;
    const int tid = threadIdx.x, lane = tid & 31, warp = tid >> 5;
    const int wm = warp >> 1, wn = warp & 1;
    const int g = lane >> 2, c4 = lane & 3;

    __shared__ float sA[2][128 * 20];
    __shared__ float sB[2][128 * 20];

    float acc[2][8][4] = {};

    const int ar = tid >> 1, ac = (tid & 1) * 8;

    int m = m0 + ar;
    int b = m >> 12, h = (m >> 10) & 3, n = m & 1023;
    const float* abase = emb_all + ((long)(b * Nc + n)) * KVc;

    int r = n0 + ar;
    const float* bbase;
    int bsz;
    if (r < 240)      { bbase = Wk + (long)r * 240;         bsz = 16; }
    else if (r < 480) { bbase = Wv + (long)(r - 240) * 240; bsz = 16; }
    else              { bbase = Wk;                          bsz = 0; }

    auto seg = [&](int j) {
        return j < 16 ? 16 * h + j
             : j < 48 ? 64 + 32 * h + (j - 16)
             : j < 112 ? 192 + 64 * h + (j - 48)
             : 448 + 128 * h + (j - 112);
    };

    auto fill = [&](int s, int k0) {
        cpasync16((uint32_t)__cvta_generic_to_shared(&sA[s][ar * 20 + ac]),     abase + seg(k0 + ac),     16);
        cpasync16((uint32_t)__cvta_generic_to_shared(&sA[s][ar * 20 + ac + 4]), abase + seg(k0 + ac + 4), 16);
        cpasync16((uint32_t)__cvta_generic_to_shared(&sB[s][ar * 20 + ac]),     bbase + k0 + ac,          bsz);
        cpasync16((uint32_t)__cvta_generic_to_shared(&sB[s][ar * 20 + ac + 4]), bbase + k0 + ac + 4,      bsz);
    };

    const int KT = Dc >> 4;   // 15
    fill(0, 0);
    asm volatile("cp.async.commit_group;\n");
    for (int kt = 0; kt < KT; kt++) {
        int cur = kt & 1;
        if (kt + 1 < KT) fill(cur ^ 1, (kt + 1) << 4);
        asm volatile("cp.async.commit_group;\n");
        asm volatile("cp.async.wait_group 1;\n");
        __syncthreads();
        const float* a_s = sA[cur];
        const float* b_s = sB[cur];
        #pragma unroll
        for (int ks = 0; ks < 16; ks += 8) {
            uint32_t af[2][4], bf[8][2];
            #pragma unroll
            for (int fm = 0; fm < 2; fm++) {
                int mb = wm * 32 + fm * 16;
                af[fm][0] = f2tf(a_s[(mb + g    ) * 20 + ks + c4]);
                af[fm][1] = f2tf(a_s[(mb + g + 8) * 20 + ks + c4]);
                af[fm][2] = f2tf(a_s[(mb + g    ) * 20 + ks + c4 + 4]);
                af[fm][3] = f2tf(a_s[(mb + g + 8) * 20 + ks + c4 + 4]);
            }
            #pragma unroll
            for (int fn = 0; fn < 8; fn++) {
                int nb = wn * 64 + fn * 8 + g;
                bf[fn][0] = f2tf(b_s[nb * 20 + ks + c4]);
                bf[fn][1] = f2tf(b_s[nb * 20 + ks + c4 + 4]);
            }
            #pragma unroll
            for (int fm = 0; fm < 2; fm++)
                #pragma unroll
                for (int fn = 0; fn < 8; fn++)
                    mma_tf32(acc[fm][fn], af[fm], bf[fn]);
        }
        __syncthreads();
    }

    #pragma unroll
    for (int fm = 0; fm < 2; fm++) {
        int row0 = wm * 32 + fm * 16 + g;
        #pragma unroll
        for (int half = 0; half < 2; half++) {
            long rr = (long)(m0 + row0 + half * 8);
            int bh_o = (int)(rr >> 10), n_o = (int)(rr & 1023);
            #pragma unroll
            for (int fn = 0; fn < 8; fn++) {
                int col = n0 + wn * 64 + fn * 8 + c4 * 2;
                float2 v = make_float2(rndtf(acc[fm][fn][half * 2]),
                                       rndtf(acc[fm][fn][half * 2 + 1]));
                if (col < 240) {
                    float* p = KhT + ((long)bh_o * 240 + col) * 1024 + n_o;
                    p[0] = v.x; p[1024] = v.y;
                } else if (col < 480) {
                    *(float2*)(Vh + rr * 240 + col - 240) = v;
                }
            }
        }
    }
}

// =======================================================================
// All-scale score GEMM with ldmatrix. z=(sc<<6)|bh, block tile 64x240 (warp span 256).
// NT: C[dd,c] = alpha * sum_n Qh[dd,n] * KhT[c,n]. Both operands pre-rounded tf32.
// =======================================================================
__global__ __launch_bounds__(256)
void score_all(const float* __restrict__ Qh, const float* __restrict__ KhT,
               float* __restrict__ S, float alpha)
{
    const int z = blockIdx.z, sc = z >> 6, bh = z & 63;
    const int d = 16 << sc;
    const int m0 = blockIdx.y * 64;
    if (m0 >= d) return;

    const float* A = Qh  + 65536L * (d - 16) + (long)bh * d * 1024;  // [d][1024]
    const float* B = KhT + (long)bh * 240 * 1024;                    // [240][1024]
    float*       C = S   + 15360L * (d - 16) + (long)bh * d * 240;   // [d][240]

    const int tid = threadIdx.x, lane = tid & 31, warp = tid >> 5;
    const int wm = warp >> 2, wn = warp & 3;      // 2 x 4 warps, warp tile 32 x 64
    const int g = lane >> 2, c4 = lane & 3;

    __shared__ float sA[2][64 * 20];
    __shared__ float sB[2][256 * 20];

    float acc[2][8][4] = {};

    const int lr = tid >> 2, lq = (tid & 3) * 4;   // loader: row, 16B quad

    auto fill = [&](int s, int k0) {
        cpasync16((uint32_t)__cvta_generic_to_shared(&sA[s][lr * 20 + lq]),
                  A + (long)(m0 + lr) * 1024 + k0 + lq, (m0 + lr < d) ? 16 : 0);
        #pragma unroll
        for (int rd = 0; rd < 4; rd++) {
            int row = lr + rd * 64;
            cpasync16((uint32_t)__cvta_generic_to_shared(&sB[s][row * 20 + lq]),
                      B + (long)row * 1024 + k0 + lq, (row < 240) ? 16 : 0);
        }
    };

    // ldmatrix per-lane address components
    const uint32_t sAb = (uint32_t)__cvta_generic_to_shared(sA);
    const uint32_t sBb = (uint32_t)__cvta_generic_to_shared(sB);
    const int a_row = wm * 32 + (lane & 15);
    const int a_kh  = (lane >> 4) * 4;
    const int b_row = wn * 64 + ((lane & 16) >> 1) + (lane & 7);
    const int b_kh  = ((lane >> 3) & 1) * 4;

    const int KT = 64;   // K = 1024, BK = 16
    fill(0, 0);
    asm volatile("cp.async.commit_group;\n");
    for (int kt = 0; kt < KT; kt++) {
        int cur = kt & 1;
        if (kt + 1 < KT) fill(cur ^ 1, (kt + 1) << 4);
        asm volatile("cp.async.commit_group;\n");
        asm volatile("cp.async.wait_group 1;\n");
        __syncthreads();
        const uint32_t aBase = sAb + (uint32_t)(cur * 64 * 20) * 4u;
        const uint32_t bBase = sBb + (uint32_t)(cur * 256 * 20) * 4u;
        #pragma unroll
        for (int ks = 0; ks < 16; ks += 8) {
            uint32_t af[2][4], bfr[16];
            #pragma unroll
            for (int fm = 0; fm < 2; fm++)
                ldsm4(af[fm], aBase + (uint32_t)((a_row + fm * 16) * 20 + ks + a_kh) * 4u);
            #pragma unroll
            for (int fp = 0; fp < 4; fp++)
                ldsm4(&bfr[fp * 4], bBase + (uint32_t)((b_row + fp * 16) * 20 + ks + b_kh) * 4u);
            #pragma unroll
            for (int fm = 0; fm < 2; fm++)
                #pragma unroll
                for (int fn = 0; fn < 8; fn++)
                    mma_tf32(acc[fm][fn], af[fm], &bfr[(fn >> 1) * 4 + (fn & 1) * 2]);
        }
        __syncthreads();
    }

    #pragma unroll
    for (int fm = 0; fm < 2; fm++) {
        int row0 = m0 + wm * 32 + fm * 16 + g;
        #pragma unroll
        for (int half = 0; half < 2; half++) {
            int r = row0 + half * 8;
            if (r >= d) continue;
            #pragma unroll
            for (int fn = 0; fn < 8; fn++) {
                int col = wn * 64 + fn * 8 + c4 * 2;
                if (col >= 240) continue;
                *(float2*)(C + (long)r * 240 + col) =
                    make_float2(alpha * acc[fm][fn][half * 2],
                                alpha * acc[fm][fn][half * 2 + 1]);
            }
        }
    }
}

// =======================================================================
// InstanceNorm stats: one block per (scale,bh); biased var, eps=1e-5.
// =======================================================================
__global__ void stats_all(const float* __restrict__ S, float* __restrict__ stats)
{
    const int i = blockIdx.x, sc = i >> 6, bh = i & 63;
    const int d = 16 << sc, dc = d - 16;
    const float* p = S + 15360L * dc + (long)bh * d * 240;
    const int count = d * 240;

    float s = 0.f, ss = 0.f;
    for (int j = threadIdx.x; j < count; j += blockDim.x) {
        float v = p[j]; s += v; ss += v * v;
    }
    __shared__ float rs[8], rss[8];
    #pragma unroll
    for (int o = 16; o; o >>= 1) {
        s  += __shfl_xor_sync(0xffffffffu, s,  o);
        ss += __shfl_xor_sync(0xffffffffu, ss, o);
    }
    int w = threadIdx.x >> 5, l = threadIdx.x & 31;
    if (l == 0) { rs[w] = s; rss[w] = ss; }
    __syncthreads();
    if (threadIdx.x == 0) {
        float a = 0.f, b2 = 0.f;
        for (int j = 0; j < 8; j++) { a += rs[j]; b2 += rss[j]; }
        float mean = a / count;
        float var  = b2 / count - mean * mean;
        stats[2 * i]     = mean;
        stats[2 * i + 1] = rsqrtf(var + 1e-5f);
    }
}

// =======================================================================
// Softmax apply: one warp per score row (240 elems); tf32-rounded probs.
// =======================================================================
__global__ __launch_bounds__(256)
void softmax_all(float* __restrict__ S, const float* __restrict__ stats)
{
    int row = blockIdx.x * 8 + (threadIdx.x >> 5);
    int l = threadIdx.x & 31;
    int sc, loc;
    if (row < 1024)      { sc = 0; loc = row; }
    else if (row < 3072) { sc = 1; loc = row - 1024; }
    else if (row < 7168) { sc = 2; loc = row - 3072; }
    else                 { sc = 3; loc = row - 7168; }
    int d = 16 << sc, dc = d - 16;
    int bh = loc >> (4 + sc);
    float* p = S + 15360L * dc + (long)loc * 240;
    float mean = stats[2 * ((sc << 6) | bh)];
    float istd = stats[2 * ((sc << 6) | bh) + 1];

    float v[8];
    float mx = -1e30f;
    #pragma unroll
    for (int t = 0; t < 8; t++) {
        int k = l + t * 32;
        float x = (k < 240) ? (p[k] - mean) * istd : -1e30f;
        v[t] = x; mx = fmaxf(mx, x);
    }
    #pragma unroll
    for (int o = 16; o; o >>= 1) mx = fmaxf(mx, __shfl_xor_sync(0xffffffffu, mx, o));
    float se = 0.f;
    #pragma unroll
    for (int t = 0; t < 8; t++) {
        int k = l + t * 32;
        float e = (k < 240) ? __expf(v[t] - mx) : 0.f;
        v[t] = e; se += e;
    }
    #pragma unroll
    for (int o = 16; o; o >>= 1) se += __shfl_xor_sync(0xffffffffu, se, o);
    float inv = 1.f / se;
    #pragma unroll
    for (int t = 0; t < 8; t++) {
        int k = l + t * 32;
        if (k < 240) p[k] = rndtf(v[t] * inv);
    }
}

extern "C" void kernel_launch(void* const* d_in, const int* in_sizes, int n_in,
                              void* d_out, int out_size)
{
    const float* emb[4]  = { (const float*)d_in[0], (const float*)d_in[1],
                             (const float*)d_in[2], (const float*)d_in[3] };
    const float* emb_all = (const float*)d_in[4];
    const float* Wq[4]   = { (const float*)d_in[5], (const float*)d_in[6],
                             (const float*)d_in[7], (const float*)d_in[8] };
    const float* Wk      = (const float*)d_in[9];
    const float* Wv      = (const float*)d_in[10];
    const float* Wo[4]   = { (const float*)d_in[11], (const float*)d_in[12],
                             (const float*)d_in[13], (const float*)d_in[14] };
    float* out = (float*)d_out;

    float *pKhT, *pVh, *pQh, *pS, *pCtxT, *pStats;
    cudaGetSymbolAddress((void**)&pKhT,   g_KhT);
    cudaGetSymbolAddress((void**)&pVh,    g_Vh);
    cudaGetSymbolAddress((void**)&pQh,    g_Qh);
    cudaGetSymbolAddress((void**)&pS,     g_S);
    cudaGetSymbolAddress((void**)&pCtxT,  g_ctxT);
    cudaGetSymbolAddress((void**)&pStats, g_stats);

    const int chArr[4] = {64, 128, 256, 512};
    const int chcum[4] = {0, 64, 192, 448};

    // 1) fused gather + K/V projection (Kh transposed)
    kvproj<<<dim3(4, 512), 256>>>(emb_all, Wk, Wv, pKhT, pVh);

    // 2) all Q projections, one launch
    qproj_all<<<dim3(16, 2, 256), 128>>>(emb[0], emb[1], emb[2], emb[3],
                                         Wq[0], Wq[1], Wq[2], Wq[3], pQh);

    const float alpha = 1.f / sqrtf((float)KVc);

    // 3) all score GEMMs, one launch (ldmatrix inner loop)
    score_all<<<dim3(1, 2, 256), 256>>>(pQh, pKhT, pS, alpha);

    // 4) instance-norm stats + softmax apply
    stats_all<<<256, 256>>>(pS, pStats);
    softmax_all<<<15360 / 8, 256>>>(pS, pStats);

    // 5) all ctx GEMMs, one launch
    ctx_all<<<dim3(16, 2, 256), 128>>>(pS, pVh, pCtxT);

    // 6) output projections
    for (int sc = 0; sc < 4; sc++) {
        int CH = chArr[sc];
        float* ctxT = pCtxT + (long)Bc * Nc * chcum[sc];
        float* Osc  = out   + (long)Bc * Nc * chcum[sc];
        if (CH >= 256) {
            dim3 grid(CH / 128, (Bc * Nc) / 128);
            gemm128<false, true><<<grid, 256>>>(ctxT, Wo[sc], Osc,
                                                Bc * Nc, CH, CH, CH, CH, CH, 1.f);
        } else {
            dim3 grid(CH / 64, (Bc * Nc) / 64, 1);
            gemm64<false, false, true, false><<<grid, 128>>>(ctxT, Wo[sc], Osc,
                Bc * Nc, CH, CH, CH, CH, CH, 1, 1,
                0, 0, 0, 0, 0, 0, 1.f);
        }
    }
}

// round 10
// speedup vs baseline: 4.3527x; 1.0520x over previous
#include <cuda_runtime.h>
#include <math.h>
#include <stdint.h>

// Problem constants
#define Bc 16
#define Nc 1024
#define Hc 4
#define KVc 960
#define Dc 240            // KV/4, per-head K/V feature dim

#define SZ_BHND (Bc*Hc*Nc*Dc)   // 15,728,640

// ---------------- scratch (static device globals; no allocation) ----------
__device__ float g_KhT [SZ_BHND];           // [bh][240][1024]  (tf32-rounded, TRANSPOSED)
__device__ float g_Vh  [SZ_BHND];           // [bh][1024][240]  (tf32-rounded)
__device__ float g_Qh  [SZ_BHND];           // per-scale [bh][d][1024] (tf32-rounded)
__device__ float g_S   [Bc*Hc*Dc*Dc];       // per-scale [bh][d][240]
__device__ float g_ctxT[Bc*Nc*KVc];         // per-scale [B,N,CH] (tf32-rounded)
__device__ float g_part[1024];              // per score-block partial (sum, sumsq)
__device__ float g_stats[512];              // per (scale,bh): mean, istd

// ---------------- helpers ----------------
__device__ __forceinline__ void cpasync16(uint32_t dst, const void* src, int sz) {
    asm volatile("cp.async.ca.shared.global [%0], [%1], 16, %2;\n"
                 :: "r"(dst), "l"(src), "r"(sz));
}
__device__ __forceinline__ uint32_t f2tf(float f) {
    uint32_t r; asm("cvt.rna.tf32.f32 %0, %1;" : "=r"(r) : "f"(f)); return r;
}
__device__ __forceinline__ float rndtf(float f) { return __uint_as_float(f2tf(f)); }

template<bool CVT>
__device__ __forceinline__ uint32_t ldop(float v) {
    return CVT ? f2tf(v) : __float_as_uint(v);
}
__device__ __forceinline__ void mma_tf32(float* acc, const uint32_t* a, const uint32_t* b) {
    asm volatile("mma.sync.aligned.m16n8k8.row.col.f32.tf32.tf32.f32 "
                 "{%0,%1,%2,%3}, {%4,%5,%6,%7}, {%8,%9}, {%0,%1,%2,%3};\n"
                 : "+f"(acc[0]), "+f"(acc[1]), "+f"(acc[2]), "+f"(acc[3])
                 : "r"(a[0]), "r"(a[1]), "r"(a[2]), "r"(a[3]), "r"(b[0]), "r"(b[1]));
}
__device__ __forceinline__ void ldsm4(uint32_t* r, uint32_t addr) {
    asm volatile("ldmatrix.sync.aligned.m8n8.x4.shared.b16 {%0,%1,%2,%3}, [%4];\n"
                 : "=r"(r[0]), "=r"(r[1]), "=r"(r[2]), "=r"(r[3]) : "r"(addr));
}

// =======================================================================
// Shared 64x64 GEMM body: 128 threads, BK=16, NT (B [Nn][K] K-contig).
// =======================================================================
template<bool SC, bool CVTA, bool CVTB, bool RND>
__device__ __forceinline__
void gemm64_body(const float* __restrict__ A, const float* __restrict__ B, float* __restrict__ C,
                 int M, int Nn, int K, int lda, int ldb, int ldc, int ldcC,
                 int m0, int n0, float alpha)
{
    const int tid = threadIdx.x, lane = tid & 31, warp = tid >> 5;
    const int wm = warp >> 1, wn = warp & 1;
    const int g = lane >> 2, c4 = lane & 3;

    __shared__ float sA[2][64 * 20];
    __shared__ float sB[2][64 * 20];

    float acc[2][4][4] = {};

    const int ar = tid >> 1, ac = (tid & 1) * 8;

    auto fill = [&](int s, int k0) {
        const float* ap = A + (long)(m0 + ar) * lda + k0 + ac;
        int sa = (m0 + ar < M) ? 16 : 0;
        cpasync16((uint32_t)__cvta_generic_to_shared(&sA[s][ar * 20 + ac]),     ap,     sa);
        cpasync16((uint32_t)__cvta_generic_to_shared(&sA[s][ar * 20 + ac + 4]), ap + 4, sa);
        const float* bp = B + (long)(n0 + ar) * ldb + k0 + ac;
        int sb = (n0 + ar < Nn) ? 16 : 0;
        cpasync16((uint32_t)__cvta_generic_to_shared(&sB[s][ar * 20 + ac]),     bp,     sb);
        cpasync16((uint32_t)__cvta_generic_to_shared(&sB[s][ar * 20 + ac + 4]), bp + 4, sb);
    };

    const int KT = K >> 4;
    fill(0, 0);
    asm volatile("cp.async.commit_group;\n");
    for (int kt = 0; kt < KT; kt++) {
        int cur = kt & 1;
        if (kt + 1 < KT) fill(cur ^ 1, (kt + 1) << 4);
        asm volatile("cp.async.commit_group;\n");
        asm volatile("cp.async.wait_group 1;\n");
        __syncthreads();
        const float* a_s = sA[cur];
        const float* b_s = sB[cur];
        #pragma unroll
        for (int ks = 0; ks < 16; ks += 8) {
            uint32_t af[2][4], bf[4][2];
            #pragma unroll
            for (int fm = 0; fm < 2; fm++) {
                int mb = wm * 32 + fm * 16;
                af[fm][0] = ldop<CVTA>(a_s[(mb + g    ) * 20 + ks + c4]);
                af[fm][1] = ldop<CVTA>(a_s[(mb + g + 8) * 20 + ks + c4]);
                af[fm][2] = ldop<CVTA>(a_s[(mb + g    ) * 20 + ks + c4 + 4]);
                af[fm][3] = ldop<CVTA>(a_s[(mb + g + 8) * 20 + ks + c4 + 4]);
            }
            #pragma unroll
            for (int fn = 0; fn < 4; fn++) {
                int nb = wn * 32 + fn * 8 + g;
                bf[fn][0] = ldop<CVTB>(b_s[nb * 20 + ks + c4]);
                bf[fn][1] = ldop<CVTB>(b_s[nb * 20 + ks + c4 + 4]);
            }
            #pragma unroll
            for (int fm = 0; fm < 2; fm++)
                #pragma unroll
                for (int fn = 0; fn < 4; fn++)
                    mma_tf32(acc[fm][fn], af[fm], bf[fn]);
        }
        __syncthreads();
    }

    #pragma unroll
    for (int fm = 0; fm < 2; fm++) {
        int row0 = m0 + wm * 32 + fm * 16 + g;
        #pragma unroll
        for (int half = 0; half < 2; half++) {
            int r = row0 + half * 8;
            if (r >= M) continue;
            #pragma unroll
            for (int fn = 0; fn < 4; fn++) {
                int col = n0 + wn * 32 + fn * 8 + c4 * 2;
                if (col >= Nn) continue;
                float v0 = alpha * acc[fm][fn][half * 2 + 0];
                float v1 = alpha * acc[fm][fn][half * 2 + 1];
                if (RND) { v0 = rndtf(v0); v1 = rndtf(v1); }
                if (SC) {
                    C[(long)r * ldc + (long)col * ldcC] = v0;
                    C[(long)r * ldc + (long)(col + 1) * ldcC] = v1;
                } else {
                    *(float2*)(C + (long)r * ldc + col) = make_float2(v0, v1);
                }
            }
        }
    }
}

// Generic 64x64 kernel (used for out-proj CH=64/128)
template<bool SC, bool CVTA, bool CVTB, bool RND>
__global__ __launch_bounds__(128)
void gemm64(const float* __restrict__ A, const float* __restrict__ B, float* __restrict__ C,
            int M, int Nn, int K, int lda, int ldb, int ldc, int ldcC, int Hs,
            long aB, long aH, long bB, long bH, long cB, long cH, float alpha)
{
    int z = blockIdx.z, zb = z / Hs, zh = z - zb * Hs;
    gemm64_body<SC, CVTA, CVTB, RND>(A + zb * aB + zh * aH, B + zb * bB + zh * bH,
                                     C + zb * cB + zh * cH,
                                     M, Nn, K, lda, ldb, ldc, ldcC,
                                     blockIdx.y * 64, blockIdx.x * 64, alpha);
}

// All-scale Q projection: z = (sc<<6)|bh. QhT[sc][bh][e][n], rounded.
__global__ __launch_bounds__(128)
void qproj_all(const float* __restrict__ e1, const float* __restrict__ e2,
               const float* __restrict__ e3, const float* __restrict__ e4,
               const float* __restrict__ w1, const float* __restrict__ w2,
               const float* __restrict__ w3, const float* __restrict__ w4,
               float* __restrict__ Qh)
{
    const int z = blockIdx.z, sc = z >> 6, bh = z & 63, b = bh >> 2, h = bh & 3;
    const int d = 16 << sc, CH = d * 4;
    const int m0 = blockIdx.y * 64;
    if (m0 >= d) return;
    const float* emb = sc == 0 ? e1 : sc == 1 ? e2 : sc == 2 ? e3 : e4;
    const float* Wq  = sc == 0 ? w1 : sc == 1 ? w2 : sc == 2 ? w3 : w4;
    const float* A = Wq + (long)h * d * d;                 // [d][d]
    const float* B = emb + (long)b * 1024 * CH + h * d;    // [1024][CH]
    float*       C = Qh + 65536L * (d - 16) + (long)bh * d * 1024;  // [d][1024]
    gemm64_body<false, true, true, true>(A, B, C, d, 1024, d, d, CH, 1024, 1,
                                         m0, blockIdx.x * 64, 1.f);
}

// All-scale ctx GEMM: z = (sc<<6)|bh. ctxT[b][n][dd*H+h], rounded.
__global__ __launch_bounds__(128)
void ctx_all(const float* __restrict__ S, const float* __restrict__ Vh,
             float* __restrict__ ctxT)
{
    const int z = blockIdx.z, sc = z >> 6, bh = z & 63, b = bh >> 2, h = bh & 3;
    const int d = 16 << sc, CH = d * 4;
    const int m0 = blockIdx.y * 64;
    if (m0 >= d) return;
    const float* A = S  + 15360L * (d - 16) + (long)bh * d * 240;   // [d][240]
    const float* B = Vh + (long)bh * 1024 * 240;                    // [1024][240]
    float*       C = ctxT + 65536L * (d - 16) + (long)b * 1024 * CH + h;
    gemm64_body<true, false, false, true>(A, B, C, d, 1024, 240, 240, 240, Hc, CH,
                                          m0, blockIdx.x * 64, 1.f);
}

// =======================================================================
// 128x128 tile, 256 threads, BK=16 — NT: C = alpha*A*B^T
// =======================================================================
template<bool CVTA, bool CVTB>
__global__ __launch_bounds__(256)
void gemm128(const float* __restrict__ A, const float* __restrict__ B, float* __restrict__ C,
             int M, int Nn, int K, int lda, int ldb, int ldc, float alpha)
{
    const int m0 = blockIdx.y * 128, n0 = blockIdx.x * 128;
    const int tid = threadIdx.x, lane = tid & 31, warp = tid >> 5;
    const int wm = warp >> 1, wn = warp & 1;   // 4x2 warps: warp tile 32x64
    const int g = lane >> 2, c4 = lane & 3;

    __shared__ float sA[2][128 * 20];
    __shared__ float sB[2][128 * 20];

    float acc[2][8][4] = {};

    const int ar = tid >> 1, ac = (tid & 1) * 8;

    auto fill = [&](int s, int k0) {
        const float* ap = A + (long)(m0 + ar) * lda + k0 + ac;
        int sa = (m0 + ar < M) ? 16 : 0;
        cpasync16((uint32_t)__cvta_generic_to_shared(&sA[s][ar * 20 + ac]),     ap,     sa);
        cpasync16((uint32_t)__cvta_generic_to_shared(&sA[s][ar * 20 + ac + 4]), ap + 4, sa);
        const float* bp = B + (long)(n0 + ar) * ldb + k0 + ac;
        int sb = (n0 + ar < Nn) ? 16 : 0;
        cpasync16((uint32_t)__cvta_generic_to_shared(&sB[s][ar * 20 + ac]),     bp,     sb);
        cpasync16((uint32_t)__cvta_generic_to_shared(&sB[s][ar * 20 + ac + 4]), bp + 4, sb);
    };

    const int KT = K >> 4;
    fill(0, 0);
    asm volatile("cp.async.commit_group;\n");
    for (int kt = 0; kt < KT; kt++) {
        int cur = kt & 1;
        if (kt + 1 < KT) fill(cur ^ 1, (kt + 1) << 4);
        asm volatile("cp.async.commit_group;\n");
        asm volatile("cp.async.wait_group 1;\n");
        __syncthreads();
        const float* a_s = sA[cur];
        const float* b_s = sB[cur];
        #pragma unroll
        for (int ks = 0; ks < 16; ks += 8) {
            uint32_t af[2][4], bf[8][2];
            #pragma unroll
            for (int fm = 0; fm < 2; fm++) {
                int mb = wm * 32 + fm * 16;
                af[fm][0] = ldop<CVTA>(a_s[(mb + g    ) * 20 + ks + c4]);
                af[fm][1] = ldop<CVTA>(a_s[(mb + g + 8) * 20 + ks + c4]);
                af[fm][2] = ldop<CVTA>(a_s[(mb + g    ) * 20 + ks + c4 + 4]);
                af[fm][3] = ldop<CVTA>(a_s[(mb + g + 8) * 20 + ks + c4 + 4]);
            }
            #pragma unroll
            for (int fn = 0; fn < 8; fn++) {
                int nb = wn * 64 + fn * 8 + g;
                bf[fn][0] = ldop<CVTB>(b_s[nb * 20 + ks + c4]);
                bf[fn][1] = ldop<CVTB>(b_s[nb * 20 + ks + c4 + 4]);
            }
            #pragma unroll
            for (int fm = 0; fm < 2; fm++)
                #pragma unroll
                for (int fn = 0; fn < 8; fn++)
                    mma_tf32(acc[fm][fn], af[fm], bf[fn]);
        }
        __syncthreads();
    }

    #pragma unroll
    for (int fm = 0; fm < 2; fm++) {
        int row0 = m0 + wm * 32 + fm * 16 + g;
        #pragma unroll
        for (int half = 0; half < 2; half++) {
            int r = row0 + half * 8;
            if (r >= M) continue;
            #pragma unroll
            for (int fn = 0; fn < 8; fn++) {
                int col = n0 + wn * 64 + fn * 8 + c4 * 2;
                if (col >= Nn) continue;
                *(float2*)(C + (long)r * ldc + col) =
                    make_float2(alpha * acc[fm][fn][half * 2], alpha * acc[fm][fn][half * 2 + 1]);
            }
        }
    }
}

// =======================================================================
// Fused gather + K/V projection (128x128 tile). Rounded outputs.
// Kh written TRANSPOSED: KhT[bh][c][n]; Vh written [bh][n][c].
// =======================================================================
__global__ __launch_bounds__(256)
void kvproj(const float* __restrict__ emb_all, const float* __restrict__ Wk,
            const float* __restrict__ Wv, float* __restrict__ KhT, float* __restrict__ Vh)
{
    const int m0 = blockIdx.y * 128, n0 = blockIdx.x * 128;
    const int tid = threadIdx.x, lane = tid & 31, warp = tid >> 5;
    const int wm = warp >> 1, wn = warp & 1;
    const int g = lane >> 2, c4 = lane & 3;

    __shared__ float sA[2][128 * 20];
    __shared__ float sB[2][128 * 20];

    float acc[2][8][4] = {};

    const int ar = tid >> 1, ac = (tid & 1) * 8;

    int m = m0 + ar;
    int b = m >> 12, h = (m >> 10) & 3, n = m & 1023;
    const float* abase = emb_all + ((long)(b * Nc + n)) * KVc;

    int r = n0 + ar;
    const float* bbase;
    int bsz;
    if (r < 240)      { bbase = Wk + (long)r * 240;         bsz = 16; }
    else if (r < 480) { bbase = Wv + (long)(r - 240) * 240; bsz = 16; }
    else              { bbase = Wk;                          bsz = 0; }

    auto seg = [&](int j) {
        return j < 16 ? 16 * h + j
             : j < 48 ? 64 + 32 * h + (j - 16)
             : j < 112 ? 192 + 64 * h + (j - 48)
             : 448 + 128 * h + (j - 112);
    };

    auto fill = [&](int s, int k0) {
        cpasync16((uint32_t)__cvta_generic_to_shared(&sA[s][ar * 20 + ac]),     abase + seg(k0 + ac),     16);
        cpasync16((uint32_t)__cvta_generic_to_shared(&sA[s][ar * 20 + ac + 4]), abase + seg(k0 + ac + 4), 16);
        cpasync16((uint32_t)__cvta_generic_to_shared(&sB[s][ar * 20 + ac]),     bbase + k0 + ac,          bsz);
        cpasync16((uint32_t)__cvta_generic_to_shared(&sB[s][ar * 20 + ac + 4]), bbase + k0 + ac + 4,      bsz);
    };

    const int KT = Dc >> 4;   // 15
    fill(0, 0);
    asm volatile("cp.async.commit_group;\n");
    for (int kt = 0; kt < KT; kt++) {
        int cur = kt & 1;
        if (kt + 1 < KT) fill(cur ^ 1, (kt + 1) << 4);
        asm volatile("cp.async.commit_group;\n");
        asm volatile("cp.async.wait_group 1;\n");
        __syncthreads();
        const float* a_s = sA[cur];
        const float* b_s = sB[cur];
        #pragma unroll
        for (int ks = 0; ks < 16; ks += 8) {
            uint32_t af[2][4], bf[8][2];
            #pragma unroll
            for (int fm = 0; fm < 2; fm++) {
                int mb = wm * 32 + fm * 16;
                af[fm][0] = f2tf(a_s[(mb + g    ) * 20 + ks + c4]);
                af[fm][1] = f2tf(a_s[(mb + g + 8) * 20 + ks + c4]);
                af[fm][2] = f2tf(a_s[(mb + g    ) * 20 + ks + c4 + 4]);
                af[fm][3] = f2tf(a_s[(mb + g + 8) * 20 + ks + c4 + 4]);
            }
            #pragma unroll
            for (int fn = 0; fn < 8; fn++) {
                int nb = wn * 64 + fn * 8 + g;
                bf[fn][0] = f2tf(b_s[nb * 20 + ks + c4]);
                bf[fn][1] = f2tf(b_s[nb * 20 + ks + c4 + 4]);
            }
            #pragma unroll
            for (int fm = 0; fm < 2; fm++)
                #pragma unroll
                for (int fn = 0; fn < 8; fn++)
                    mma_tf32(acc[fm][fn], af[fm], bf[fn]);
        }
        __syncthreads();
    }

    #pragma unroll
    for (int fm = 0; fm < 2; fm++) {
        int row0 = wm * 32 + fm * 16 + g;
        #pragma unroll
        for (int half = 0; half < 2; half++) {
            long rr = (long)(m0 + row0 + half * 8);
            int bh_o = (int)(rr >> 10), n_o = (int)(rr & 1023);
            #pragma unroll
            for (int fn = 0; fn < 8; fn++) {
                int col = n0 + wn * 64 + fn * 8 + c4 * 2;
                float2 v = make_float2(rndtf(acc[fm][fn][half * 2]),
                                       rndtf(acc[fm][fn][half * 2 + 1]));
                if (col < 240) {
                    float* p = KhT + ((long)bh_o * 240 + col) * 1024 + n_o;
                    p[0] = v.x; p[1024] = v.y;
                } else if (col < 480) {
                    *(float2*)(Vh + rr * 240 + col - 240) = v;
                }
            }
        }
    }
}

// =======================================================================
// All-scale score GEMM with ldmatrix + fused stats partials.
// z=(sc<<6)|bh, block tile 64x240. NT: C[dd,c] = alpha * sum_n Qh[dd,n]*KhT[c,n].
// Each block also reduces sum/sumsq of its stored tile into g_part.
// =======================================================================
__global__ __launch_bounds__(256)
void score_all(const float* __restrict__ Qh, const float* __restrict__ KhT,
               float* __restrict__ S, float* __restrict__ part, float alpha)
{
    const int z = blockIdx.z, sc = z >> 6, bh = z & 63;
    const int d = 16 << sc;
    const int m0 = blockIdx.y * 64;
    if (m0 >= d) return;

    const float* A = Qh  + 65536L * (d - 16) + (long)bh * d * 1024;  // [d][1024]
    const float* B = KhT + (long)bh * 240 * 1024;                    // [240][1024]
    float*       C = S   + 15360L * (d - 16) + (long)bh * d * 240;   // [d][240]

    const int tid = threadIdx.x, lane = tid & 31, warp = tid >> 5;
    const int wm = warp >> 2, wn = warp & 3;      // 2 x 4 warps, warp tile 32 x 64
    const int g = lane >> 2, c4 = lane & 3;

    __shared__ float sA[2][64 * 20];
    __shared__ float sB[2][256 * 20];
    __shared__ float red[16];

    float acc[2][8][4] = {};

    const int lr = tid >> 2, lq = (tid & 3) * 4;   // loader: row, 16B quad

    auto fill = [&](int s, int k0) {
        cpasync16((uint32_t)__cvta_generic_to_shared(&sA[s][lr * 20 + lq]),
                  A + (long)(m0 + lr) * 1024 + k0 + lq, (m0 + lr < d) ? 16 : 0);
        #pragma unroll
        for (int rd = 0; rd < 4; rd++) {
            int row = lr + rd * 64;
            cpasync16((uint32_t)__cvta_generic_to_shared(&sB[s][row * 20 + lq]),
                      B + (long)row * 1024 + k0 + lq, (row < 240) ? 16 : 0);
        }
    };

    // ldmatrix per-lane address components
    const uint32_t sAb = (uint32_t)__cvta_generic_to_shared(sA);
    const uint32_t sBb = (uint32_t)__cvta_generic_to_shared(sB);
    const int a_row = wm * 32 + (lane & 15);
    const int a_kh  = (lane >> 4) * 4;
    const int b_row = wn * 64 + ((lane & 16) >> 1) + (lane & 7);
    const int b_kh  = ((lane >> 3) & 1) * 4;

    const int KT = 64;   // K = 1024, BK = 16
    fill(0, 0);
    asm volatile("cp.async.commit_group;\n");
    for (int kt = 0; kt < KT; kt++) {
        int cur = kt & 1;
        if (kt + 1 < KT) fill(cur ^ 1, (kt + 1) << 4);
        asm volatile("cp.async.commit_group;\n");
        asm volatile("cp.async.wait_group 1;\n");
        __syncthreads();
        const uint32_t aBase = sAb + (uint32_t)(cur * 64 * 20) * 4u;
        const uint32_t bBase = sBb + (uint32_t)(cur * 256 * 20) * 4u;
        #pragma unroll
        for (int ks = 0; ks < 16; ks += 8) {
            uint32_t af[2][4], bfr[16];
            #pragma unroll
            for (int fm = 0; fm < 2; fm++)
                ldsm4(af[fm], aBase + (uint32_t)((a_row + fm * 16) * 20 + ks + a_kh) * 4u);
            #pragma unroll
            for (int fp = 0; fp < 4; fp++)
                ldsm4(&bfr[fp * 4], bBase + (uint32_t)((b_row + fp * 16) * 20 + ks + b_kh) * 4u);
            #pragma unroll
            for (int fm = 0; fm < 2; fm++)
                #pragma unroll
                for (int fn = 0; fn < 8; fn++)
                    mma_tf32(acc[fm][fn], af[fm], &bfr[(fn >> 1) * 4 + (fn & 1) * 2]);
        }
        __syncthreads();
    }

    float ls = 0.f, lss = 0.f;
    #pragma unroll
    for (int fm = 0; fm < 2; fm++) {
        int row0 = m0 + wm * 32 + fm * 16 + g;
        #pragma unroll
        for (int half = 0; half < 2; half++) {
            int r = row0 + half * 8;
            if (r >= d) continue;
            #pragma unroll
            for (int fn = 0; fn < 8; fn++) {
                int col = wn * 64 + fn * 8 + c4 * 2;
                if (col >= 240) continue;
                float v0 = alpha * acc[fm][fn][half * 2];
                float v1 = alpha * acc[fm][fn][half * 2 + 1];
                *(float2*)(C + (long)r * 240 + col) = make_float2(v0, v1);
                ls  += v0 + v1;
                lss += v0 * v0 + v1 * v1;
            }
        }
    }

    // block reduction of (ls, lss) — fixed order, deterministic
    #pragma unroll
    for (int o = 16; o; o >>= 1) {
        ls  += __shfl_xor_sync(0xffffffffu, ls,  o);
        lss += __shfl_xor_sync(0xffffffffu, lss, o);
    }
    if (lane == 0) { red[warp] = ls; red[8 + warp] = lss; }
    __syncthreads();
    if (tid == 0) {
        float s = 0.f, ss = 0.f;
        #pragma unroll
        for (int j = 0; j < 8; j++) { s += red[j]; ss += red[8 + j]; }
        int idx = z * 2 + blockIdx.y;
        part[2 * idx]     = s;
        part[2 * idx + 1] = ss;
    }
}

// Combine score-block partials into per-(scale,bh) mean/istd. One block, 256 threads.
__global__ void stats_combine(const float* __restrict__ part, float* __restrict__ stats)
{
    int i = threadIdx.x;            // (sc<<6)|bh
    int sc = i >> 6;
    int d = 16 << sc;
    int nb = (d > 64) ? 2 : 1;
    float s = 0.f, ss = 0.f;
    for (int j = 0; j < nb; j++) {
        s  += part[2 * (i * 2 + j)];
        ss += part[2 * (i * 2 + j) + 1];
    }
    float count = (float)(d * 240);
    float mean = s / count;
    float var  = ss / count - mean * mean;
    stats[2 * i]     = mean;
    stats[2 * i + 1] = rsqrtf(var + 1e-5f);
}

// =======================================================================
// Softmax apply: one warp per score row (240 elems); tf32-rounded probs.
// =======================================================================
__global__ __launch_bounds__(256)
void softmax_all(float* __restrict__ S, const float* __restrict__ stats)
{
    int row = blockIdx.x * 8 + (threadIdx.x >> 5);
    int l = threadIdx.x & 31;
    int sc, loc;
    if (row < 1024)      { sc = 0; loc = row; }
    else if (row < 3072) { sc = 1; loc = row - 1024; }
    else if (row < 7168) { sc = 2; loc = row - 3072; }
    else                 { sc = 3; loc = row - 7168; }
    int d = 16 << sc, dc = d - 16;
    int bh = loc >> (4 + sc);
    float* p = S + 15360L * dc + (long)loc * 240;
    float mean = stats[2 * ((sc << 6) | bh)];
    float istd = stats[2 * ((sc << 6) | bh) + 1];

    float v[8];
    float mx = -1e30f;
    #pragma unroll
    for (int t = 0; t < 8; t++) {
        int k = l + t * 32;
        float x = (k < 240) ? (p[k] - mean) * istd : -1e30f;
        v[t] = x; mx = fmaxf(mx, x);
    }
    #pragma unroll
    for (int o = 16; o; o >>= 1) mx = fmaxf(mx, __shfl_xor_sync(0xffffffffu, mx, o));
    float se = 0.f;
    #pragma unroll
    for (int t = 0; t < 8; t++) {
        int k = l + t * 32;
        float e = (k < 240) ? __expf(v[t] - mx) : 0.f;
        v[t] = e; se += e;
    }
    #pragma unroll
    for (int o = 16; o; o >>= 1) se += __shfl_xor_sync(0xffffffffu, se, o);
    float inv = 1.f / se;
    #pragma unroll
    for (int t = 0; t < 8; t++) {
        int k = l + t * 32;
        if (k < 240) p[k] = rndtf(v[t] * inv);
    }
}

extern "C" void kernel_launch(void* const* d_in, const int* in_sizes, int n_in,
                              void* d_out, int out_size)
{
    const float* emb[4]  = { (const float*)d_in[0], (const float*)d_in[1],
                             (const float*)d_in[2], (const float*)d_in[3] };
    const float* emb_all = (const float*)d_in[4];
    const float* Wq[4]   = { (const float*)d_in[5], (const float*)d_in[6],
                             (const float*)d_in[7], (const float*)d_in[8] };
    const float* Wk      = (const float*)d_in[9];
    const float* Wv      = (const float*)d_in[10];
    const float* Wo[4]   = { (const float*)d_in[11], (const float*)d_in[12],
                             (const float*)d_in[13], (const float*)d_in[14] };
    float* out = (float*)d_out;

    float *pKhT, *pVh, *pQh, *pS, *pCtxT, *pPart, *pStats;
    cudaGetSymbolAddress((void**)&pKhT,   g_KhT);
    cudaGetSymbolAddress((void**)&pVh,    g_Vh);
    cudaGetSymbolAddress((void**)&pQh,    g_Qh);
    cudaGetSymbolAddress((void**)&pS,     g_S);
    cudaGetSymbolAddress((void**)&pCtxT,  g_ctxT);
    cudaGetSymbolAddress((void**)&pPart,  g_part);
    cudaGetSymbolAddress((void**)&pStats, g_stats);

    const int chArr[4] = {64, 128, 256, 512};
    const int chcum[4] = {0, 64, 192, 448};

    // 1) fused gather + K/V projection (Kh transposed)
    kvproj<<<dim3(4, 512), 256>>>(emb_all, Wk, Wv, pKhT, pVh);

    // 2) all Q projections, one launch
    qproj_all<<<dim3(16, 2, 256), 128>>>(emb[0], emb[1], emb[2], emb[3],
                                         Wq[0], Wq[1], Wq[2], Wq[3], pQh);

    const float alpha = 1.f / sqrtf((float)KVc);

    // 3) all score GEMMs, one launch (ldmatrix + fused stats partials)
    score_all<<<dim3(1, 2, 256), 256>>>(pQh, pKhT, pS, pPart, alpha);

    // 4) combine partials -> mean/istd; softmax apply
    stats_combine<<<1, 256>>>(pPart, pStats);
    softmax_all<<<15360 / 8, 256>>>(pS, pStats);

    // 5) all ctx GEMMs, one launch
    ctx_all<<<dim3(16, 2, 256), 128>>>(pS, pVh, pCtxT);

    // 6) output projections
    for (int sc = 0; sc < 4; sc++) {
        int CH = chArr[sc];
        float* ctxT = pCtxT + (long)Bc * Nc * chcum[sc];
        float* Osc  = out   + (long)Bc * Nc * chcum[sc];
        if (CH >= 256) {
            dim3 grid(CH / 128, (Bc * Nc) / 128);
            gemm128<false, true><<<grid, 256>>>(ctxT, Wo[sc], Osc,
                                                Bc * Nc, CH, CH, CH, CH, CH, 1.f);
        } else {
            dim3 grid(CH / 64, (Bc * Nc) / 64, 1);
            gemm64<false, false, true, false><<<grid, 128>>>(ctxT, Wo[sc], Osc,
                Bc * Nc, CH, CH, CH, CH, CH, 1, 1,
                0, 0, 0, 0, 0, 0, 1.f);
        }
    }
}